// round 11
// baseline (speedup 1.0000x reference)
#include <cuda_runtime.h>
#include <cuda_bf16.h>
#include <cstdint>

// Problem constants
#define B_   16
#define T_   2048
#define DIN  1024
#define DPRJ 512
#define DOUT 1024
#define LORD 20
#define MROWS (B_ * T_)          // 32768

// ---------------------------------------------------------------------------
// Device scratch (allocation-free)
// ---------------------------------------------------------------------------
__device__ float g_x[(size_t)MROWS * DPRJ];                 // x fp32 (conv in, out_cache)
__device__ __nv_bfloat16 g_a1h[(size_t)MROWS * DIN];        // input split hi
__device__ __nv_bfloat16 g_a1l[(size_t)MROWS * DIN];        // input split lo
__device__ __nv_bfloat16 g_mh[(size_t)MROWS * DPRJ];        // m split hi
__device__ __nv_bfloat16 g_ml[(size_t)MROWS * DPRJ];        // m split lo
// Transposed, split weights: rows = N dim, K contiguous
__device__ __nv_bfloat16 g_b1h[(size_t)DPRJ * DIN];         // [512][1024]
__device__ __nv_bfloat16 g_b1l[(size_t)DPRJ * DIN];
__device__ __nv_bfloat16 g_b2h[(size_t)DOUT * DPRJ];        // [1024][512]
__device__ __nv_bfloat16 g_b2l[(size_t)DOUT * DPRJ];

__device__ __forceinline__ float4 ld4(const float* p) {
    return *reinterpret_cast<const float4*>(p);
}

__device__ __forceinline__ uint32_t smem_u32(const void* p) {
    uint32_t a;
    asm("{ .reg .u64 t; cvta.to.shared.u64 t, %1; cvt.u32.u64 %0, t; }"
        : "=r"(a) : "l"(p));
    return a;
}

// cp.async 16B global -> shared
__device__ __forceinline__ void cp16(uint32_t dst, const void* src) {
    asm volatile("cp.async.cg.shared.global [%0], [%1], 16;"
                 :: "r"(dst), "l"(src));
}
#define CP_COMMIT() asm volatile("cp.async.commit_group;" ::: "memory")
template <int N>
__device__ __forceinline__ void cp_wait() {
    asm volatile("cp.async.wait_group %0;" :: "n"(N) : "memory");
}

// ldmatrix x4 (four 8x8 b16 matrices)
__device__ __forceinline__ void ldsm4(uint32_t* r, uint32_t addr) {
    asm volatile("ldmatrix.sync.aligned.m8n8.x4.shared.b16 {%0,%1,%2,%3}, [%4];"
                 : "=r"(r[0]), "=r"(r[1]), "=r"(r[2]), "=r"(r[3])
                 : "r"(addr));
}

// mma.sync m16n8k16 bf16 -> f32
__device__ __forceinline__ void mma_bf16(float* c, const uint32_t* a,
                                         uint32_t b0, uint32_t b1) {
    asm volatile(
        "mma.sync.aligned.m16n8k16.row.col.f32.bf16.bf16.f32 "
        "{%0,%1,%2,%3}, {%4,%5,%6,%7}, {%8,%9}, {%0,%1,%2,%3};"
        : "+f"(c[0]), "+f"(c[1]), "+f"(c[2]), "+f"(c[3])
        : "r"(a[0]), "r"(a[1]), "r"(a[2]), "r"(a[3]), "r"(b0), "r"(b1));
}

// ---------------------------------------------------------------------------
// Tensor-core GEMM via mma.sync: C[M,N] = A[M,K] * B^T (bf16 3-term split)
// All operands pre-split bf16 in GMEM. cp.async 3-stage pipeline.
// CTA 128x128, KC=32, 256 threads (8 warps, 2x4), warp tile 64x32.
// SMEM stage: Ah, Al, Bh, Bl each [128][40] bf16 (stride-40 padding).
// ---------------------------------------------------------------------------
#define KC        32
#define STR       40
#define TEN_BYTES (128 * STR * 2)         // 10240
#define STG_BYTES (4 * TEN_BYTES)         // 40960
#define STAGES    3

template <bool RELU>
__global__ __launch_bounds__(256)
void gemm_mma(int M, int N, int K,
              const __nv_bfloat16* __restrict__ Ahg_,
              const __nv_bfloat16* __restrict__ Alg_,
              const __nv_bfloat16* __restrict__ Bhg_,
              const __nv_bfloat16* __restrict__ Blg_,
              const float* __restrict__ bias,
              float* __restrict__ C)
{
    extern __shared__ char smem_raw[];
    const uint32_t sb = smem_u32(smem_raw);

    const int tid  = threadIdx.x;
    const int lane = tid & 31;
    const int wid  = tid >> 5;
    const int warpM = wid >> 2;           // 0..1
    const int warpN = wid & 3;            // 0..3
    const int nt = blockIdx.x;
    const int mt = blockIdx.y;
    const int NKC = K / KC;

    const __nv_bfloat16* Ahg = Ahg_ + (size_t)mt * 128 * K;
    const __nv_bfloat16* Alg = Alg_ + (size_t)mt * 128 * K;
    const __nv_bfloat16* Bhg = Bhg_ + (size_t)nt * 128 * K;
    const __nv_bfloat16* Blg = Blg_ + (size_t)nt * 128 * K;

    float acc[4][4][4];
    #pragma unroll
    for (int i = 0; i < 4; i++)
        #pragma unroll
        for (int j = 0; j < 4; j++)
            #pragma unroll
            for (int q = 0; q < 4; q++) acc[i][j][q] = 0.f;

    // per-thread cp.async coordinates: 2 chunks of 16B per tensor
    // chunk i in 0..511: row r = i>>2 (0..127), c8 = i&3 (k = c8*8)
    const int r0  = tid >> 2,  c80  = tid & 3;
    const int r1  = (tid + 256) >> 2, c81 = (tid + 256) & 3;
    const uint32_t so0 = (uint32_t)(r0 * 80 + c80 * 16);
    const uint32_t so1 = (uint32_t)(r1 * 80 + c81 * 16);

    auto issue = [&](int slot, int kc) {
        const uint32_t st = sb + slot * STG_BYTES;
        const size_t g0 = (size_t)r0 * K + kc * KC + c80 * 8;
        const size_t g1 = (size_t)r1 * K + kc * KC + c81 * 8;
        cp16(st + so0,                 Ahg + g0);
        cp16(st + so1,                 Ahg + g1);
        cp16(st + TEN_BYTES + so0,     Alg + g0);
        cp16(st + TEN_BYTES + so1,     Alg + g1);
        cp16(st + 2 * TEN_BYTES + so0, Bhg + g0);
        cp16(st + 2 * TEN_BYTES + so1, Bhg + g1);
        cp16(st + 3 * TEN_BYTES + so0, Blg + g0);
        cp16(st + 3 * TEN_BYTES + so1, Blg + g1);
        CP_COMMIT();
    };

    const int lr = lane & 15;
    const int lc = lane >> 4;

    auto compute = [&](int slot) {
        const uint32_t sAh = sb + slot * STG_BYTES;
        const uint32_t sAl = sAh + TEN_BYTES;
        const uint32_t sBh = sAh + 2 * TEN_BYTES;
        const uint32_t sBl = sAh + 3 * TEN_BYTES;
        #pragma unroll
        for (int ks = 0; ks < KC; ks += 16) {
            uint32_t ah[4][4], al[4][4], bh[2][4], bl[2][4];
            #pragma unroll
            for (int i = 0; i < 4; i++) {
                const uint32_t ao =
                    ((warpM * 64 + i * 16 + lr) * STR + ks + lc * 8) * 2;
                ldsm4(ah[i], sAh + ao);
                ldsm4(al[i], sAl + ao);
            }
            #pragma unroll
            for (int jj = 0; jj < 2; jj++) {
                const uint32_t bo =
                    ((warpN * 32 + jj * 16 + lr) * STR + ks + lc * 8) * 2;
                ldsm4(bh[jj], sBh + bo);
                ldsm4(bl[jj], sBl + bo);
            }
            #pragma unroll
            for (int i = 0; i < 4; i++) {
                #pragma unroll
                for (int j = 0; j < 4; j++) {
                    const int jj = j >> 1, sel = j & 1;
                    const uint32_t b0h = bh[jj][sel], b1h = bh[jj][sel + 2];
                    mma_bf16(acc[i][j], ah[i], b0h, b1h);                       // Ah*Bh
                    mma_bf16(acc[i][j], al[i], b0h, b1h);                       // Al*Bh
                    mma_bf16(acc[i][j], ah[i], bl[jj][sel], bl[jj][sel + 2]);   // Ah*Bl
                }
            }
        }
    };

    // ---- 3-stage cp.async pipeline, one sync per chunk ----
    issue(0, 0);
    issue(1, 1);
    for (int kc = 0; kc < NKC; kc++) {
        cp_wait<STAGES - 2>();
        __syncthreads();                      // stage kc%3 ready; stage (kc+2)%3 free
        const int nk = kc + STAGES - 1;
        if (nk < NKC) issue(nk % STAGES, nk); // overlaps with compute below
        compute(kc % STAGES);
    }

    // ---- epilogue ----
    #pragma unroll
    for (int i = 0; i < 4; i++) {
        const int row0 = mt * 128 + warpM * 64 + i * 16 + (lane >> 2);
        #pragma unroll
        for (int j = 0; j < 4; j++) {
            const int col = nt * 128 + warpN * 32 + j * 8 + (lane & 3) * 2;
            float2 v0, v1;
            v0.x = acc[i][j][0]; v0.y = acc[i][j][1];   // row0
            v1.x = acc[i][j][2]; v1.y = acc[i][j][3];   // row0 + 8
            if (RELU) {
                const float b0 = bias[col], b1 = bias[col + 1];
                v0.x = fmaxf(v0.x + b0, 0.f); v0.y = fmaxf(v0.y + b1, 0.f);
                v1.x = fmaxf(v1.x + b0, 0.f); v1.y = fmaxf(v1.y + b1, 0.f);
            }
            *reinterpret_cast<float2*>(C + (size_t)row0 * N + col)       = v0;
            *reinterpret_cast<float2*>(C + (size_t)(row0 + 8) * N + col) = v1;
        }
    }
}

// ---------------------------------------------------------------------------
// Input pre-split: fp32 -> bf16 hi/lo (vectorized)
// ---------------------------------------------------------------------------
__global__ void split_input(const float* __restrict__ in,
                            __nv_bfloat16* __restrict__ h,
                            __nv_bfloat16* __restrict__ l)
{
    const size_t i4 = (size_t)blockIdx.x * 256 + threadIdx.x;  // float4 index
    const float4 v = ld4(in + i4 * 4);
    __nv_bfloat16 hx = __float2bfloat16(v.x);
    __nv_bfloat16 hy = __float2bfloat16(v.y);
    __nv_bfloat16 hz = __float2bfloat16(v.z);
    __nv_bfloat16 hw = __float2bfloat16(v.w);
    __nv_bfloat16 lx = __float2bfloat16(v.x - __bfloat162float(hx));
    __nv_bfloat16 ly = __float2bfloat16(v.y - __bfloat162float(hy));
    __nv_bfloat16 lz = __float2bfloat16(v.z - __bfloat162float(hz));
    __nv_bfloat16 lw = __float2bfloat16(v.w - __bfloat162float(hw));
    uint2 hv, lv;
    hv.x = (uint32_t)__bfloat16_as_ushort(hx) | ((uint32_t)__bfloat16_as_ushort(hy) << 16);
    hv.y = (uint32_t)__bfloat16_as_ushort(hz) | ((uint32_t)__bfloat16_as_ushort(hw) << 16);
    lv.x = (uint32_t)__bfloat16_as_ushort(lx) | ((uint32_t)__bfloat16_as_ushort(ly) << 16);
    lv.y = (uint32_t)__bfloat16_as_ushort(lz) | ((uint32_t)__bfloat16_as_ushort(lw) << 16);
    *reinterpret_cast<uint2*>(h + i4 * 4) = hv;
    *reinterpret_cast<uint2*>(l + i4 * 4) = lv;
}

// ---------------------------------------------------------------------------
// Weight prep: transpose + bf16 hi/lo split
// ---------------------------------------------------------------------------
__global__ void prep_w1(const float* __restrict__ W,   // W_lin [1024,512]
                        __nv_bfloat16* __restrict__ bh,
                        __nv_bfloat16* __restrict__ bl)
{
    const int idx = blockIdx.x * 256 + threadIdx.x;
    if (idx >= DPRJ * DIN) return;
    const int n = idx / DIN, k = idx % DIN;
    const float v = W[(size_t)k * DPRJ + n];
    const __nv_bfloat16 h = __float2bfloat16(v);
    bh[idx] = h;
    bl[idx] = __float2bfloat16(v - __bfloat162float(h));
}

__global__ void prep_w2(const float* __restrict__ W,   // W_aff [512,1024]
                        __nv_bfloat16* __restrict__ bh,
                        __nv_bfloat16* __restrict__ bl)
{
    const int idx = blockIdx.x * 256 + threadIdx.x;
    if (idx >= DOUT * DPRJ) return;
    const int o = idx / DPRJ, p = idx % DPRJ;
    const float v = W[(size_t)p * DOUT + o];
    const __nv_bfloat16 h = __float2bfloat16(v);
    bh[idx] = h;
    bl[idx] = __float2bfloat16(v - __bfloat162float(h));
}

// ---------------------------------------------------------------------------
// Depthwise causal conv (L=20) + residual; emits m as bf16 hi/lo directly
// ---------------------------------------------------------------------------
#define TCHUNK 128

__global__ __launch_bounds__(256)
void conv_residual_kernel(const float* __restrict__ x,
                          const float* __restrict__ in_cache,
                          const float* __restrict__ conv_w,
                          __nv_bfloat16* __restrict__ mh,
                          __nv_bfloat16* __restrict__ ml)
{
    const int p  = blockIdx.x * 256 + threadIdx.x;
    const int b  = blockIdx.z;
    const int t0 = blockIdx.y * TCHUNK;

    float w[LORD];
    #pragma unroll
    for (int l = 0; l < LORD; l++) w[l] = conv_w[p * LORD + l];

    float win[LORD - 1];
    #pragma unroll
    for (int i = 0; i < LORD - 1; i++) {
        const int j = t0 - (LORD - 1) + i;
        if (j >= 0)
            win[i] = x[((size_t)b * T_ + j) * DPRJ + p];
        else
            win[i] = in_cache[((size_t)b * DPRJ + p) * (LORD - 1) + (j + LORD - 1)];
    }

    const float* xrow = x  + ((size_t)b * T_ + t0) * DPRJ + p;
    __nv_bfloat16* mhrow = mh + ((size_t)b * T_ + t0) * DPRJ + p;
    __nv_bfloat16* mlrow = ml + ((size_t)b * T_ + t0) * DPRJ + p;

    for (int t = 0; t < TCHUNK; t++) {
        const float xv = xrow[(size_t)t * DPRJ];
        float acc = fmaf(w[LORD - 1], xv, xv);
        #pragma unroll
        for (int l = 0; l < LORD - 1; l++)
            acc = fmaf(w[l], win[l], acc);
        const __nv_bfloat16 h = __float2bfloat16(acc);
        mhrow[(size_t)t * DPRJ] = h;
        mlrow[(size_t)t * DPRJ] = __float2bfloat16(acc - __bfloat162float(h));
        #pragma unroll
        for (int i = 0; i < LORD - 2; i++) win[i] = win[i + 1];
        win[LORD - 2] = xv;
    }
}

__global__ void cache_kernel(const float* __restrict__ x,
                             float* __restrict__ out_cache)
{
    const int idx = blockIdx.x * blockDim.x + threadIdx.x;
    const int total = B_ * DPRJ * (LORD - 1);
    if (idx >= total) return;
    const int i = idx % (LORD - 1);
    const int p = (idx / (LORD - 1)) % DPRJ;
    const int b = idx / ((LORD - 1) * DPRJ);
    out_cache[idx] = x[((size_t)b * T_ + (T_ - (LORD - 1) + i)) * DPRJ + p];
}

// ---------------------------------------------------------------------------
extern "C" void kernel_launch(void* const* d_in, const int* in_sizes, int n_in,
                              void* d_out, int out_size)
{
    const float* input    = (const float*)d_in[0];  // [16, 2048, 1024]
    const float* in_cache = (const float*)d_in[1];  // [16, 512, 19]
    const float* W_lin    = (const float*)d_in[2];  // [1024, 512]
    const float* conv_w   = (const float*)d_in[3];  // [512, 20]
    const float* W_aff    = (const float*)d_in[4];  // [512, 1024]
    const float* b_aff    = (const float*)d_in[5];  // [1024]

    float* out       = (float*)d_out;
    float* out_cache = out + (size_t)B_ * T_ * DOUT;

    float *xbuf;
    __nv_bfloat16 *a1h, *a1l, *mh, *ml, *b1h, *b1l, *b2h, *b2l;
    cudaGetSymbolAddress((void**)&xbuf, g_x);
    cudaGetSymbolAddress((void**)&a1h, g_a1h);
    cudaGetSymbolAddress((void**)&a1l, g_a1l);
    cudaGetSymbolAddress((void**)&mh,  g_mh);
    cudaGetSymbolAddress((void**)&ml,  g_ml);
    cudaGetSymbolAddress((void**)&b1h, g_b1h);
    cudaGetSymbolAddress((void**)&b1l, g_b1l);
    cudaGetSymbolAddress((void**)&b2h, g_b2h);
    cudaGetSymbolAddress((void**)&b2l, g_b2l);

    const int SMEM_SZ = STAGES * STG_BYTES;   // 122880 B
    cudaFuncSetAttribute(gemm_mma<false>, cudaFuncAttributeMaxDynamicSharedMemorySize, SMEM_SZ);
    cudaFuncSetAttribute(gemm_mma<true>,  cudaFuncAttributeMaxDynamicSharedMemorySize, SMEM_SZ);

    // 0) operand prep: input split + weight transpose/split
    split_input<<<(MROWS * (size_t)DIN / 4 + 255) / 256, 256>>>(input, a1h, a1l);
    prep_w1<<<(DPRJ * DIN + 255) / 256, 256>>>(W_lin, b1h, b1l);
    prep_w2<<<(DOUT * DPRJ + 255) / 256, 256>>>(W_aff, b2h, b2l);

    // 1) x = input @ W_lin      M=32768, N=512, K=1024
    {
        dim3 grid(DPRJ / 128, MROWS / 128);
        gemm_mma<false><<<grid, 256, SMEM_SZ>>>(MROWS, DPRJ, DIN,
                                                a1h, a1l, b1h, b1l, nullptr, xbuf);
    }

    // 2) m = depthwise_conv(x) + x  (bf16 split out) ; out_cache
    {
        dim3 grid(DPRJ / 256, T_ / TCHUNK, B_);
        conv_residual_kernel<<<grid, 256>>>(xbuf, in_cache, conv_w, mh, ml);
        const int total = B_ * DPRJ * (LORD - 1);
        cache_kernel<<<(total + 255) / 256, 256>>>(xbuf, out_cache);
    }

    // 3) out = relu(m @ W_aff + b_aff)   M=32768, N=1024, K=512
    {
        dim3 grid(DOUT / 128, MROWS / 128);
        gemm_mma<true><<<grid, 256, SMEM_SZ>>>(MROWS, DOUT, DPRJ,
                                               mh, ml, b2h, b2l, b_aff, out);
    }
}

// round 12
// speedup vs baseline: 1.0009x; 1.0009x over previous
#include <cuda_runtime.h>
#include <cuda_bf16.h>
#include <cstdint>

// Problem constants
#define B_   16
#define T_   2048
#define DIN  1024
#define DPRJ 512
#define DOUT 1024
#define LORD 20
#define MROWS (B_ * T_)          // 32768

// ---------------------------------------------------------------------------
// Device scratch (allocation-free)
// ---------------------------------------------------------------------------
__device__ float g_x[(size_t)MROWS * DPRJ];                 // x fp32 (conv in, out_cache)
__device__ __nv_bfloat16 g_a1h[(size_t)MROWS * DIN];        // input split hi
__device__ __nv_bfloat16 g_a1l[(size_t)MROWS * DIN];        // input split lo
__device__ __nv_bfloat16 g_mh[(size_t)MROWS * DPRJ];        // m split hi
__device__ __nv_bfloat16 g_ml[(size_t)MROWS * DPRJ];        // m split lo
// Transposed, split weights: rows = N dim, K contiguous
__device__ __nv_bfloat16 g_b1h[(size_t)DPRJ * DIN];         // [512][1024]
__device__ __nv_bfloat16 g_b1l[(size_t)DPRJ * DIN];
__device__ __nv_bfloat16 g_b2h[(size_t)DOUT * DPRJ];        // [1024][512]
__device__ __nv_bfloat16 g_b2l[(size_t)DOUT * DPRJ];

__device__ __forceinline__ float4 ld4(const float* p) {
    return *reinterpret_cast<const float4*>(p);
}

__device__ __forceinline__ uint32_t smem_u32(const void* p) {
    uint32_t a;
    asm("{ .reg .u64 t; cvta.to.shared.u64 t, %1; cvt.u32.u64 %0, t; }"
        : "=r"(a) : "l"(p));
    return a;
}

// cp.async 16B global -> shared
__device__ __forceinline__ void cp16(uint32_t dst, const void* src) {
    asm volatile("cp.async.cg.shared.global [%0], [%1], 16;"
                 :: "r"(dst), "l"(src));
}
#define CP_COMMIT() asm volatile("cp.async.commit_group;" ::: "memory")
template <int N>
__device__ __forceinline__ void cp_wait() {
    asm volatile("cp.async.wait_group %0;" :: "n"(N) : "memory");
}

// ldmatrix x4 (four 8x8 b16 matrices)
__device__ __forceinline__ void ldsm4(uint32_t* r, uint32_t addr) {
    asm volatile("ldmatrix.sync.aligned.m8n8.x4.shared.b16 {%0,%1,%2,%3}, [%4];"
                 : "=r"(r[0]), "=r"(r[1]), "=r"(r[2]), "=r"(r[3])
                 : "r"(addr));
}

// mma.sync m16n8k16 bf16 -> f32
__device__ __forceinline__ void mma_bf16(float* c, const uint32_t* a,
                                         uint32_t b0, uint32_t b1) {
    asm volatile(
        "mma.sync.aligned.m16n8k16.row.col.f32.bf16.bf16.f32 "
        "{%0,%1,%2,%3}, {%4,%5,%6,%7}, {%8,%9}, {%0,%1,%2,%3};"
        : "+f"(c[0]), "+f"(c[1]), "+f"(c[2]), "+f"(c[3])
        : "r"(a[0]), "r"(a[1]), "r"(a[2]), "r"(a[3]), "r"(b0), "r"(b1));
}

// ---------------------------------------------------------------------------
// Tensor-core GEMM via mma.sync: C[M,N] = A[M,K] * B^T (bf16 3-term split)
// All operands pre-split bf16 in GMEM. cp.async 3-stage pipeline.
// CTA 128x128, KC=32, 256 threads (8 warps, 2x4), warp tile 64x32.
// SMEM stage: Ah, Al, Bh, Bl each [128][40] bf16 (stride-40 padding).
// ---------------------------------------------------------------------------
#define KC        32
#define STR       40
#define TEN_BYTES (128 * STR * 2)         // 10240
#define STG_BYTES (4 * TEN_BYTES)         // 40960
#define STAGES    3

template <bool RELU>
__global__ __launch_bounds__(256)
void gemm_mma(int M, int N, int K,
              const __nv_bfloat16* __restrict__ Ahg_,
              const __nv_bfloat16* __restrict__ Alg_,
              const __nv_bfloat16* __restrict__ Bhg_,
              const __nv_bfloat16* __restrict__ Blg_,
              const float* __restrict__ bias,
              float* __restrict__ C)
{
    extern __shared__ char smem_raw[];
    const uint32_t sb = smem_u32(smem_raw);

    const int tid  = threadIdx.x;
    const int lane = tid & 31;
    const int wid  = tid >> 5;
    const int warpM = wid >> 2;           // 0..1
    const int warpN = wid & 3;            // 0..3
    const int nt = blockIdx.x;
    const int mt = blockIdx.y;
    const int NKC = K / KC;

    const __nv_bfloat16* Ahg = Ahg_ + (size_t)mt * 128 * K;
    const __nv_bfloat16* Alg = Alg_ + (size_t)mt * 128 * K;
    const __nv_bfloat16* Bhg = Bhg_ + (size_t)nt * 128 * K;
    const __nv_bfloat16* Blg = Blg_ + (size_t)nt * 128 * K;

    float acc[4][4][4];
    #pragma unroll
    for (int i = 0; i < 4; i++)
        #pragma unroll
        for (int j = 0; j < 4; j++)
            #pragma unroll
            for (int q = 0; q < 4; q++) acc[i][j][q] = 0.f;

    // per-thread cp.async coordinates: 2 chunks of 16B per tensor
    // chunk i in 0..511: row r = i>>2 (0..127), c8 = i&3 (k = c8*8)
    const int r0  = tid >> 2,  c80  = tid & 3;
    const int r1  = (tid + 256) >> 2, c81 = (tid + 256) & 3;
    const uint32_t so0 = (uint32_t)(r0 * 80 + c80 * 16);
    const uint32_t so1 = (uint32_t)(r1 * 80 + c81 * 16);

    auto issue = [&](int slot, int kc) {
        const uint32_t st = sb + slot * STG_BYTES;
        const size_t g0 = (size_t)r0 * K + kc * KC + c80 * 8;
        const size_t g1 = (size_t)r1 * K + kc * KC + c81 * 8;
        cp16(st + so0,                 Ahg + g0);
        cp16(st + so1,                 Ahg + g1);
        cp16(st + TEN_BYTES + so0,     Alg + g0);
        cp16(st + TEN_BYTES + so1,     Alg + g1);
        cp16(st + 2 * TEN_BYTES + so0, Bhg + g0);
        cp16(st + 2 * TEN_BYTES + so1, Bhg + g1);
        cp16(st + 3 * TEN_BYTES + so0, Blg + g0);
        cp16(st + 3 * TEN_BYTES + so1, Blg + g1);
        CP_COMMIT();
    };

    const int lr = lane & 15;
    const int lc = lane >> 4;

    auto compute = [&](int slot) {
        const uint32_t sAh = sb + slot * STG_BYTES;
        const uint32_t sAl = sAh + TEN_BYTES;
        const uint32_t sBh = sAh + 2 * TEN_BYTES;
        const uint32_t sBl = sAh + 3 * TEN_BYTES;
        #pragma unroll
        for (int ks = 0; ks < KC; ks += 16) {
            uint32_t ah[4][4], al[4][4], bh[2][4], bl[2][4];
            #pragma unroll
            for (int i = 0; i < 4; i++) {
                const uint32_t ao =
                    ((warpM * 64 + i * 16 + lr) * STR + ks + lc * 8) * 2;
                ldsm4(ah[i], sAh + ao);
                ldsm4(al[i], sAl + ao);
            }
            #pragma unroll
            for (int jj = 0; jj < 2; jj++) {
                const uint32_t bo =
                    ((warpN * 32 + jj * 16 + lr) * STR + ks + lc * 8) * 2;
                ldsm4(bh[jj], sBh + bo);
                ldsm4(bl[jj], sBl + bo);
            }
            #pragma unroll
            for (int i = 0; i < 4; i++) {
                #pragma unroll
                for (int j = 0; j < 4; j++) {
                    const int jj = j >> 1, sel = j & 1;
                    const uint32_t b0h = bh[jj][sel], b1h = bh[jj][sel + 2];
                    mma_bf16(acc[i][j], ah[i], b0h, b1h);                       // Ah*Bh
                    mma_bf16(acc[i][j], al[i], b0h, b1h);                       // Al*Bh
                    mma_bf16(acc[i][j], ah[i], bl[jj][sel], bl[jj][sel + 2]);   // Ah*Bl
                }
            }
        }
    };

    // ---- 3-stage cp.async pipeline, one sync per chunk ----
    issue(0, 0);
    issue(1, 1);
    for (int kc = 0; kc < NKC; kc++) {
        cp_wait<STAGES - 2>();
        __syncthreads();                      // stage kc%3 ready; stage (kc+2)%3 free
        const int nk = kc + STAGES - 1;
        if (nk < NKC) issue(nk % STAGES, nk); // overlaps with compute below
        compute(kc % STAGES);
    }

    // ---- epilogue ----
    #pragma unroll
    for (int i = 0; i < 4; i++) {
        const int row0 = mt * 128 + warpM * 64 + i * 16 + (lane >> 2);
        #pragma unroll
        for (int j = 0; j < 4; j++) {
            const int col = nt * 128 + warpN * 32 + j * 8 + (lane & 3) * 2;
            float2 v0, v1;
            v0.x = acc[i][j][0]; v0.y = acc[i][j][1];   // row0
            v1.x = acc[i][j][2]; v1.y = acc[i][j][3];   // row0 + 8
            if (RELU) {
                const float b0 = bias[col], b1 = bias[col + 1];
                v0.x = fmaxf(v0.x + b0, 0.f); v0.y = fmaxf(v0.y + b1, 0.f);
                v1.x = fmaxf(v1.x + b0, 0.f); v1.y = fmaxf(v1.y + b1, 0.f);
            }
            *reinterpret_cast<float2*>(C + (size_t)row0 * N + col)       = v0;
            *reinterpret_cast<float2*>(C + (size_t)(row0 + 8) * N + col) = v1;
        }
    }
}

// ---------------------------------------------------------------------------
// Input pre-split: fp32 -> bf16 hi/lo (vectorized)
// ---------------------------------------------------------------------------
__global__ void split_input(const float* __restrict__ in,
                            __nv_bfloat16* __restrict__ h,
                            __nv_bfloat16* __restrict__ l)
{
    const size_t i4 = (size_t)blockIdx.x * 256 + threadIdx.x;  // float4 index
    const float4 v = ld4(in + i4 * 4);
    __nv_bfloat16 hx = __float2bfloat16(v.x);
    __nv_bfloat16 hy = __float2bfloat16(v.y);
    __nv_bfloat16 hz = __float2bfloat16(v.z);
    __nv_bfloat16 hw = __float2bfloat16(v.w);
    __nv_bfloat16 lx = __float2bfloat16(v.x - __bfloat162float(hx));
    __nv_bfloat16 ly = __float2bfloat16(v.y - __bfloat162float(hy));
    __nv_bfloat16 lz = __float2bfloat16(v.z - __bfloat162float(hz));
    __nv_bfloat16 lw = __float2bfloat16(v.w - __bfloat162float(hw));
    uint2 hv, lv;
    hv.x = (uint32_t)__bfloat16_as_ushort(hx) | ((uint32_t)__bfloat16_as_ushort(hy) << 16);
    hv.y = (uint32_t)__bfloat16_as_ushort(hz) | ((uint32_t)__bfloat16_as_ushort(hw) << 16);
    lv.x = (uint32_t)__bfloat16_as_ushort(lx) | ((uint32_t)__bfloat16_as_ushort(ly) << 16);
    lv.y = (uint32_t)__bfloat16_as_ushort(lz) | ((uint32_t)__bfloat16_as_ushort(lw) << 16);
    *reinterpret_cast<uint2*>(h + i4 * 4) = hv;
    *reinterpret_cast<uint2*>(l + i4 * 4) = lv;
}

// ---------------------------------------------------------------------------
// Weight prep: transpose + bf16 hi/lo split
// ---------------------------------------------------------------------------
__global__ void prep_w1(const float* __restrict__ W,   // W_lin [1024,512]
                        __nv_bfloat16* __restrict__ bh,
                        __nv_bfloat16* __restrict__ bl)
{
    const int idx = blockIdx.x * 256 + threadIdx.x;
    if (idx >= DPRJ * DIN) return;
    const int n = idx / DIN, k = idx % DIN;
    const float v = W[(size_t)k * DPRJ + n];
    const __nv_bfloat16 h = __float2bfloat16(v);
    bh[idx] = h;
    bl[idx] = __float2bfloat16(v - __bfloat162float(h));
}

__global__ void prep_w2(const float* __restrict__ W,   // W_aff [512,1024]
                        __nv_bfloat16* __restrict__ bh,
                        __nv_bfloat16* __restrict__ bl)
{
    const int idx = blockIdx.x * 256 + threadIdx.x;
    if (idx >= DOUT * DPRJ) return;
    const int o = idx / DPRJ, p = idx % DPRJ;
    const float v = W[(size_t)p * DOUT + o];
    const __nv_bfloat16 h = __float2bfloat16(v);
    bh[idx] = h;
    bl[idx] = __float2bfloat16(v - __bfloat162float(h));
}

// ---------------------------------------------------------------------------
// Depthwise causal conv (L=20) + residual; emits m as bf16 hi/lo directly
// ---------------------------------------------------------------------------
#define TCHUNK 128

__global__ __launch_bounds__(256)
void conv_residual_kernel(const float* __restrict__ x,
                          const float* __restrict__ in_cache,
                          const float* __restrict__ conv_w,
                          __nv_bfloat16* __restrict__ mh,
                          __nv_bfloat16* __restrict__ ml)
{
    const int p  = blockIdx.x * 256 + threadIdx.x;
    const int b  = blockIdx.z;
    const int t0 = blockIdx.y * TCHUNK;

    float w[LORD];
    #pragma unroll
    for (int l = 0; l < LORD; l++) w[l] = conv_w[p * LORD + l];

    float win[LORD - 1];
    #pragma unroll
    for (int i = 0; i < LORD - 1; i++) {
        const int j = t0 - (LORD - 1) + i;
        if (j >= 0)
            win[i] = x[((size_t)b * T_ + j) * DPRJ + p];
        else
            win[i] = in_cache[((size_t)b * DPRJ + p) * (LORD - 1) + (j + LORD - 1)];
    }

    const float* xrow = x  + ((size_t)b * T_ + t0) * DPRJ + p;
    __nv_bfloat16* mhrow = mh + ((size_t)b * T_ + t0) * DPRJ + p;
    __nv_bfloat16* mlrow = ml + ((size_t)b * T_ + t0) * DPRJ + p;

    for (int t = 0; t < TCHUNK; t++) {
        const float xv = xrow[(size_t)t * DPRJ];
        float acc = fmaf(w[LORD - 1], xv, xv);
        #pragma unroll
        for (int l = 0; l < LORD - 1; l++)
            acc = fmaf(w[l], win[l], acc);
        const __nv_bfloat16 h = __float2bfloat16(acc);
        mhrow[(size_t)t * DPRJ] = h;
        mlrow[(size_t)t * DPRJ] = __float2bfloat16(acc - __bfloat162float(h));
        #pragma unroll
        for (int i = 0; i < LORD - 2; i++) win[i] = win[i + 1];
        win[LORD - 2] = xv;
    }
}

__global__ void cache_kernel(const float* __restrict__ x,
                             float* __restrict__ out_cache)
{
    const int idx = blockIdx.x * blockDim.x + threadIdx.x;
    const int total = B_ * DPRJ * (LORD - 1);
    if (idx >= total) return;
    const int i = idx % (LORD - 1);
    const int p = (idx / (LORD - 1)) % DPRJ;
    const int b = idx / ((LORD - 1) * DPRJ);
    out_cache[idx] = x[((size_t)b * T_ + (T_ - (LORD - 1) + i)) * DPRJ + p];
}

// ---------------------------------------------------------------------------
extern "C" void kernel_launch(void* const* d_in, const int* in_sizes, int n_in,
                              void* d_out, int out_size)
{
    const float* input    = (const float*)d_in[0];  // [16, 2048, 1024]
    const float* in_cache = (const float*)d_in[1];  // [16, 512, 19]
    const float* W_lin    = (const float*)d_in[2];  // [1024, 512]
    const float* conv_w   = (const float*)d_in[3];  // [512, 20]
    const float* W_aff    = (const float*)d_in[4];  // [512, 1024]
    const float* b_aff    = (const float*)d_in[5];  // [1024]

    float* out       = (float*)d_out;
    float* out_cache = out + (size_t)B_ * T_ * DOUT;

    float *xbuf;
    __nv_bfloat16 *a1h, *a1l, *mh, *ml, *b1h, *b1l, *b2h, *b2l;
    cudaGetSymbolAddress((void**)&xbuf, g_x);
    cudaGetSymbolAddress((void**)&a1h, g_a1h);
    cudaGetSymbolAddress((void**)&a1l, g_a1l);
    cudaGetSymbolAddress((void**)&mh,  g_mh);
    cudaGetSymbolAddress((void**)&ml,  g_ml);
    cudaGetSymbolAddress((void**)&b1h, g_b1h);
    cudaGetSymbolAddress((void**)&b1l, g_b1l);
    cudaGetSymbolAddress((void**)&b2h, g_b2h);
    cudaGetSymbolAddress((void**)&b2l, g_b2l);

    const int SMEM_SZ = STAGES * STG_BYTES;   // 122880 B
    cudaFuncSetAttribute(gemm_mma<false>, cudaFuncAttributeMaxDynamicSharedMemorySize, SMEM_SZ);
    cudaFuncSetAttribute(gemm_mma<true>,  cudaFuncAttributeMaxDynamicSharedMemorySize, SMEM_SZ);

    // 0) operand prep: input split + weight transpose/split
    split_input<<<(MROWS * (size_t)DIN / 4 + 255) / 256, 256>>>(input, a1h, a1l);
    prep_w1<<<(DPRJ * DIN + 255) / 256, 256>>>(W_lin, b1h, b1l);
    prep_w2<<<(DOUT * DPRJ + 255) / 256, 256>>>(W_aff, b2h, b2l);

    // 1) x = input @ W_lin      M=32768, N=512, K=1024
    {
        dim3 grid(DPRJ / 128, MROWS / 128);
        gemm_mma<false><<<grid, 256, SMEM_SZ>>>(MROWS, DPRJ, DIN,
                                                a1h, a1l, b1h, b1l, nullptr, xbuf);
    }

    // 2) m = depthwise_conv(x) + x  (bf16 split out) ; out_cache
    {
        dim3 grid(DPRJ / 256, T_ / TCHUNK, B_);
        conv_residual_kernel<<<grid, 256>>>(xbuf, in_cache, conv_w, mh, ml);
        const int total = B_ * DPRJ * (LORD - 1);
        cache_kernel<<<(total + 255) / 256, 256>>>(xbuf, out_cache);
    }

    // 3) out = relu(m @ W_aff + b_aff)   M=32768, N=1024, K=512
    {
        dim3 grid(DOUT / 128, MROWS / 128);
        gemm_mma<true><<<grid, 256, SMEM_SZ>>>(MROWS, DOUT, DPRJ,
                                               mh, ml, b2h, b2l, b_aff, out);
    }
}

// round 13
// speedup vs baseline: 1.1126x; 1.1116x over previous
#include <cuda_runtime.h>
#include <cuda_bf16.h>
#include <cstdint>

// Problem constants
#define B_   16
#define T_   2048
#define DIN  1024
#define DPRJ 512
#define DOUT 1024
#define LORD 20
#define MROWS (B_ * T_)          // 32768

// ---------------------------------------------------------------------------
// Device scratch (allocation-free)
// ---------------------------------------------------------------------------
__device__ float g_x[(size_t)MROWS * DPRJ];                 // x fp32 (conv in, out_cache)
__device__ __nv_bfloat16 g_a1h[(size_t)MROWS * DIN];        // input split hi
__device__ __nv_bfloat16 g_a1l[(size_t)MROWS * DIN];        // input split lo
__device__ __nv_bfloat16 g_mh[(size_t)MROWS * DPRJ];        // m split hi
__device__ __nv_bfloat16 g_ml[(size_t)MROWS * DPRJ];        // m split lo
// Transposed, split weights: rows = N dim, K contiguous
__device__ __nv_bfloat16 g_b1h[(size_t)DPRJ * DIN];         // [512][1024]
__device__ __nv_bfloat16 g_b1l[(size_t)DPRJ * DIN];
__device__ __nv_bfloat16 g_b2h[(size_t)DOUT * DPRJ];        // [1024][512]
__device__ __nv_bfloat16 g_b2l[(size_t)DOUT * DPRJ];

__device__ __forceinline__ float4 ld4(const float* p) {
    return *reinterpret_cast<const float4*>(p);
}

__device__ __forceinline__ uint32_t smem_u32(const void* p) {
    uint32_t a;
    asm("{ .reg .u64 t; cvta.to.shared.u64 t, %1; cvt.u32.u64 %0, t; }"
        : "=r"(a) : "l"(p));
    return a;
}

// cp.async 16B global -> shared
__device__ __forceinline__ void cp16(uint32_t dst, const void* src) {
    asm volatile("cp.async.cg.shared.global [%0], [%1], 16;"
                 :: "r"(dst), "l"(src));
}
#define CP_COMMIT() asm volatile("cp.async.commit_group;" ::: "memory")
template <int N>
__device__ __forceinline__ void cp_wait() {
    asm volatile("cp.async.wait_group %0;" :: "n"(N) : "memory");
}

// ldmatrix x4 (four 8x8 b16 matrices)
__device__ __forceinline__ void ldsm4(uint32_t* r, uint32_t addr) {
    asm volatile("ldmatrix.sync.aligned.m8n8.x4.shared.b16 {%0,%1,%2,%3}, [%4];"
                 : "=r"(r[0]), "=r"(r[1]), "=r"(r[2]), "=r"(r[3])
                 : "r"(addr));
}

// mma.sync m16n8k16 bf16 -> f32
__device__ __forceinline__ void mma_bf16(float* c, const uint32_t* a,
                                         uint32_t b0, uint32_t b1) {
    asm volatile(
        "mma.sync.aligned.m16n8k16.row.col.f32.bf16.bf16.f32 "
        "{%0,%1,%2,%3}, {%4,%5,%6,%7}, {%8,%9}, {%0,%1,%2,%3};"
        : "+f"(c[0]), "+f"(c[1]), "+f"(c[2]), "+f"(c[3])
        : "r"(a[0]), "r"(a[1]), "r"(a[2]), "r"(a[3]), "r"(b0), "r"(b1));
}

// ---------------------------------------------------------------------------
// Tensor-core GEMM via mma.sync: C[M,N] = A[M,K] * B^T (bf16 3-term split)
// All operands pre-split bf16 in GMEM. cp.async DOUBLE-buffered, 2 CTAs/SM.
// CTA 128x128, KC=32, 256 threads (8 warps, 2x4), warp tile 64x32.
// SMEM stage: Ah, Al, Bh, Bl each [128][40] bf16 (stride-40 padding).
// ---------------------------------------------------------------------------
#define KC        32
#define STR       40
#define TEN_BYTES (128 * STR * 2)         // 10240
#define STG_BYTES (4 * TEN_BYTES)         // 40960
#define STAGES    2                       // 81920 B total -> 2 CTAs/SM

template <bool RELU>
__global__ __launch_bounds__(256, 2)
void gemm_mma(int M, int N, int K,
              const __nv_bfloat16* __restrict__ Ahg_,
              const __nv_bfloat16* __restrict__ Alg_,
              const __nv_bfloat16* __restrict__ Bhg_,
              const __nv_bfloat16* __restrict__ Blg_,
              const float* __restrict__ bias,
              float* __restrict__ C)
{
    extern __shared__ char smem_raw[];
    const uint32_t sb = smem_u32(smem_raw);

    const int tid  = threadIdx.x;
    const int lane = tid & 31;
    const int wid  = tid >> 5;
    const int warpM = wid >> 2;           // 0..1
    const int warpN = wid & 3;            // 0..3
    const int nt = blockIdx.x;
    const int mt = blockIdx.y;
    const int NKC = K / KC;

    const __nv_bfloat16* Ahg = Ahg_ + (size_t)mt * 128 * K;
    const __nv_bfloat16* Alg = Alg_ + (size_t)mt * 128 * K;
    const __nv_bfloat16* Bhg = Bhg_ + (size_t)nt * 128 * K;
    const __nv_bfloat16* Blg = Blg_ + (size_t)nt * 128 * K;

    float acc[4][4][4];
    #pragma unroll
    for (int i = 0; i < 4; i++)
        #pragma unroll
        for (int j = 0; j < 4; j++)
            #pragma unroll
            for (int q = 0; q < 4; q++) acc[i][j][q] = 0.f;

    // per-thread cp.async coordinates: 2 chunks of 16B per tensor
    const int r0  = tid >> 2,  c80  = tid & 3;
    const int r1  = (tid + 256) >> 2, c81 = (tid + 256) & 3;
    const uint32_t so0 = (uint32_t)(r0 * 80 + c80 * 16);
    const uint32_t so1 = (uint32_t)(r1 * 80 + c81 * 16);

    auto issue = [&](int slot, int kc) {
        const uint32_t st = sb + slot * STG_BYTES;
        const size_t g0 = (size_t)r0 * K + kc * KC + c80 * 8;
        const size_t g1 = (size_t)r1 * K + kc * KC + c81 * 8;
        cp16(st + so0,                 Ahg + g0);
        cp16(st + so1,                 Ahg + g1);
        cp16(st + TEN_BYTES + so0,     Alg + g0);
        cp16(st + TEN_BYTES + so1,     Alg + g1);
        cp16(st + 2 * TEN_BYTES + so0, Bhg + g0);
        cp16(st + 2 * TEN_BYTES + so1, Bhg + g1);
        cp16(st + 3 * TEN_BYTES + so0, Blg + g0);
        cp16(st + 3 * TEN_BYTES + so1, Blg + g1);
        CP_COMMIT();
    };

    const int lr = lane & 15;
    const int lc = lane >> 4;

    auto compute = [&](int slot) {
        const uint32_t sAh = sb + slot * STG_BYTES;
        const uint32_t sAl = sAh + TEN_BYTES;
        const uint32_t sBh = sAh + 2 * TEN_BYTES;
        const uint32_t sBl = sAh + 3 * TEN_BYTES;
        #pragma unroll
        for (int ks = 0; ks < KC; ks += 16) {
            uint32_t ah[4][4], al[4][4], bh[2][4], bl[2][4];
            #pragma unroll
            for (int i = 0; i < 4; i++) {
                const uint32_t ao =
                    ((warpM * 64 + i * 16 + lr) * STR + ks + lc * 8) * 2;
                ldsm4(ah[i], sAh + ao);
                ldsm4(al[i], sAl + ao);
            }
            #pragma unroll
            for (int jj = 0; jj < 2; jj++) {
                const uint32_t bo =
                    ((warpN * 32 + jj * 16 + lr) * STR + ks + lc * 8) * 2;
                ldsm4(bh[jj], sBh + bo);
                ldsm4(bl[jj], sBl + bo);
            }
            #pragma unroll
            for (int i = 0; i < 4; i++) {
                #pragma unroll
                for (int j = 0; j < 4; j++) {
                    const int jj = j >> 1, sel = j & 1;
                    const uint32_t b0h = bh[jj][sel], b1h = bh[jj][sel + 2];
                    mma_bf16(acc[i][j], ah[i], b0h, b1h);                       // Ah*Bh
                    mma_bf16(acc[i][j], al[i], b0h, b1h);                       // Al*Bh
                    mma_bf16(acc[i][j], ah[i], bl[jj][sel], bl[jj][sel + 2]);   // Ah*Bl
                }
            }
        }
    };

    // ---- double-buffered cp.async pipeline (race-free order) ----
    // Per chunk: wait-all -> sync -> issue(kc+1) -> compute(kc).
    // issue(kc+1) writes the buffer compute(kc-1) used; the barrier at the
    // top of this iteration ordered all warps past compute(kc-1).
    issue(0, 0);
    for (int kc = 0; kc < NKC; kc++) {
        cp_wait<0>();
        __syncthreads();
        if (kc + 1 < NKC) issue((kc + 1) & 1, kc + 1);   // overlaps compute(kc)
        compute(kc & 1);
    }

    // ---- epilogue ----
    #pragma unroll
    for (int i = 0; i < 4; i++) {
        const int row0 = mt * 128 + warpM * 64 + i * 16 + (lane >> 2);
        #pragma unroll
        for (int j = 0; j < 4; j++) {
            const int col = nt * 128 + warpN * 32 + j * 8 + (lane & 3) * 2;
            float2 v0, v1;
            v0.x = acc[i][j][0]; v0.y = acc[i][j][1];   // row0
            v1.x = acc[i][j][2]; v1.y = acc[i][j][3];   // row0 + 8
            if (RELU) {
                const float b0 = bias[col], b1 = bias[col + 1];
                v0.x = fmaxf(v0.x + b0, 0.f); v0.y = fmaxf(v0.y + b1, 0.f);
                v1.x = fmaxf(v1.x + b0, 0.f); v1.y = fmaxf(v1.y + b1, 0.f);
            }
            *reinterpret_cast<float2*>(C + (size_t)row0 * N + col)       = v0;
            *reinterpret_cast<float2*>(C + (size_t)(row0 + 8) * N + col) = v1;
        }
    }
}

// ---------------------------------------------------------------------------
// Input pre-split: fp32 -> bf16 hi/lo (vectorized)
// ---------------------------------------------------------------------------
__global__ void split_input(const float* __restrict__ in,
                            __nv_bfloat16* __restrict__ h,
                            __nv_bfloat16* __restrict__ l)
{
    const size_t i4 = (size_t)blockIdx.x * 256 + threadIdx.x;  // float4 index
    const float4 v = ld4(in + i4 * 4);
    __nv_bfloat16 hx = __float2bfloat16(v.x);
    __nv_bfloat16 hy = __float2bfloat16(v.y);
    __nv_bfloat16 hz = __float2bfloat16(v.z);
    __nv_bfloat16 hw = __float2bfloat16(v.w);
    __nv_bfloat16 lx = __float2bfloat16(v.x - __bfloat162float(hx));
    __nv_bfloat16 ly = __float2bfloat16(v.y - __bfloat162float(hy));
    __nv_bfloat16 lz = __float2bfloat16(v.z - __bfloat162float(hz));
    __nv_bfloat16 lw = __float2bfloat16(v.w - __bfloat162float(hw));
    uint2 hv, lv;
    hv.x = (uint32_t)__bfloat16_as_ushort(hx) | ((uint32_t)__bfloat16_as_ushort(hy) << 16);
    hv.y = (uint32_t)__bfloat16_as_ushort(hz) | ((uint32_t)__bfloat16_as_ushort(hw) << 16);
    lv.x = (uint32_t)__bfloat16_as_ushort(lx) | ((uint32_t)__bfloat16_as_ushort(ly) << 16);
    lv.y = (uint32_t)__bfloat16_as_ushort(lz) | ((uint32_t)__bfloat16_as_ushort(lw) << 16);
    *reinterpret_cast<uint2*>(h + i4 * 4) = hv;
    *reinterpret_cast<uint2*>(l + i4 * 4) = lv;
}

// ---------------------------------------------------------------------------
// Weight prep: transpose + bf16 hi/lo split
// ---------------------------------------------------------------------------
__global__ void prep_w1(const float* __restrict__ W,   // W_lin [1024,512]
                        __nv_bfloat16* __restrict__ bh,
                        __nv_bfloat16* __restrict__ bl)
{
    const int idx = blockIdx.x * 256 + threadIdx.x;
    if (idx >= DPRJ * DIN) return;
    const int n = idx / DIN, k = idx % DIN;
    const float v = W[(size_t)k * DPRJ + n];
    const __nv_bfloat16 h = __float2bfloat16(v);
    bh[idx] = h;
    bl[idx] = __float2bfloat16(v - __bfloat162float(h));
}

__global__ void prep_w2(const float* __restrict__ W,   // W_aff [512,1024]
                        __nv_bfloat16* __restrict__ bh,
                        __nv_bfloat16* __restrict__ bl)
{
    const int idx = blockIdx.x * 256 + threadIdx.x;
    if (idx >= DOUT * DPRJ) return;
    const int o = idx / DPRJ, p = idx % DPRJ;
    const float v = W[(size_t)p * DOUT + o];
    const __nv_bfloat16 h = __float2bfloat16(v);
    bh[idx] = h;
    bl[idx] = __float2bfloat16(v - __bfloat162float(h));
}

// ---------------------------------------------------------------------------
// Depthwise causal conv (L=20) + residual; emits m as bf16 hi/lo directly
// ---------------------------------------------------------------------------
#define TCHUNK 128

__global__ __launch_bounds__(256)
void conv_residual_kernel(const float* __restrict__ x,
                          const float* __restrict__ in_cache,
                          const float* __restrict__ conv_w,
                          __nv_bfloat16* __restrict__ mh,
                          __nv_bfloat16* __restrict__ ml)
{
    const int p  = blockIdx.x * 256 + threadIdx.x;
    const int b  = blockIdx.z;
    const int t0 = blockIdx.y * TCHUNK;

    float w[LORD];
    #pragma unroll
    for (int l = 0; l < LORD; l++) w[l] = conv_w[p * LORD + l];

    float win[LORD - 1];
    #pragma unroll
    for (int i = 0; i < LORD - 1; i++) {
        const int j = t0 - (LORD - 1) + i;
        if (j >= 0)
            win[i] = x[((size_t)b * T_ + j) * DPRJ + p];
        else
            win[i] = in_cache[((size_t)b * DPRJ + p) * (LORD - 1) + (j + LORD - 1)];
    }

    const float* xrow = x  + ((size_t)b * T_ + t0) * DPRJ + p;
    __nv_bfloat16* mhrow = mh + ((size_t)b * T_ + t0) * DPRJ + p;
    __nv_bfloat16* mlrow = ml + ((size_t)b * T_ + t0) * DPRJ + p;

    for (int t = 0; t < TCHUNK; t++) {
        const float xv = xrow[(size_t)t * DPRJ];
        float acc = fmaf(w[LORD - 1], xv, xv);
        #pragma unroll
        for (int l = 0; l < LORD - 1; l++)
            acc = fmaf(w[l], win[l], acc);
        const __nv_bfloat16 h = __float2bfloat16(acc);
        mhrow[(size_t)t * DPRJ] = h;
        mlrow[(size_t)t * DPRJ] = __float2bfloat16(acc - __bfloat162float(h));
        #pragma unroll
        for (int i = 0; i < LORD - 2; i++) win[i] = win[i + 1];
        win[LORD - 2] = xv;
    }
}

__global__ void cache_kernel(const float* __restrict__ x,
                             float* __restrict__ out_cache)
{
    const int idx = blockIdx.x * blockDim.x + threadIdx.x;
    const int total = B_ * DPRJ * (LORD - 1);
    if (idx >= total) return;
    const int i = idx % (LORD - 1);
    const int p = (idx / (LORD - 1)) % DPRJ;
    const int b = idx / ((LORD - 1) * DPRJ);
    out_cache[idx] = x[((size_t)b * T_ + (T_ - (LORD - 1) + i)) * DPRJ + p];
}

// ---------------------------------------------------------------------------
extern "C" void kernel_launch(void* const* d_in, const int* in_sizes, int n_in,
                              void* d_out, int out_size)
{
    const float* input    = (const float*)d_in[0];  // [16, 2048, 1024]
    const float* in_cache = (const float*)d_in[1];  // [16, 512, 19]
    const float* W_lin    = (const float*)d_in[2];  // [1024, 512]
    const float* conv_w   = (const float*)d_in[3];  // [512, 20]
    const float* W_aff    = (const float*)d_in[4];  // [512, 1024]
    const float* b_aff    = (const float*)d_in[5];  // [1024]

    float* out       = (float*)d_out;
    float* out_cache = out + (size_t)B_ * T_ * DOUT;

    float *xbuf;
    __nv_bfloat16 *a1h, *a1l, *mh, *ml, *b1h, *b1l, *b2h, *b2l;
    cudaGetSymbolAddress((void**)&xbuf, g_x);
    cudaGetSymbolAddress((void**)&a1h, g_a1h);
    cudaGetSymbolAddress((void**)&a1l, g_a1l);
    cudaGetSymbolAddress((void**)&mh,  g_mh);
    cudaGetSymbolAddress((void**)&ml,  g_ml);
    cudaGetSymbolAddress((void**)&b1h, g_b1h);
    cudaGetSymbolAddress((void**)&b1l, g_b1l);
    cudaGetSymbolAddress((void**)&b2h, g_b2h);
    cudaGetSymbolAddress((void**)&b2l, g_b2l);

    const int SMEM_SZ = STAGES * STG_BYTES;   // 81920 B -> 2 CTAs/SM
    cudaFuncSetAttribute(gemm_mma<false>, cudaFuncAttributeMaxDynamicSharedMemorySize, SMEM_SZ);
    cudaFuncSetAttribute(gemm_mma<true>,  cudaFuncAttributeMaxDynamicSharedMemorySize, SMEM_SZ);

    // 0) operand prep: input split + weight transpose/split
    split_input<<<(MROWS * (size_t)DIN / 4 + 255) / 256, 256>>>(input, a1h, a1l);
    prep_w1<<<(DPRJ * DIN + 255) / 256, 256>>>(W_lin, b1h, b1l);
    prep_w2<<<(DOUT * DPRJ + 255) / 256, 256>>>(W_aff, b2h, b2l);

    // 1) x = input @ W_lin      M=32768, N=512, K=1024
    {
        dim3 grid(DPRJ / 128, MROWS / 128);
        gemm_mma<false><<<grid, 256, SMEM_SZ>>>(MROWS, DPRJ, DIN,
                                                a1h, a1l, b1h, b1l, nullptr, xbuf);
    }

    // 2) m = depthwise_conv(x) + x  (bf16 split out) ; out_cache
    {
        dim3 grid(DPRJ / 256, T_ / TCHUNK, B_);
        conv_residual_kernel<<<grid, 256>>>(xbuf, in_cache, conv_w, mh, ml);
        const int total = B_ * DPRJ * (LORD - 1);
        cache_kernel<<<(total + 255) / 256, 256>>>(xbuf, out_cache);
    }

    // 3) out = relu(m @ W_aff + b_aff)   M=32768, N=1024, K=512
    {
        dim3 grid(DOUT / 128, MROWS / 128);
        gemm_mma<true><<<grid, 256, SMEM_SZ>>>(MROWS, DOUT, DPRJ,
                                               mh, ml, b2h, b2l, b_aff, out);
    }
}

// round 14
// speedup vs baseline: 1.2600x; 1.1325x over previous
#include <cuda_runtime.h>
#include <cuda_bf16.h>
#include <cstdint>

// Problem constants
#define B_   16
#define T_   2048
#define DIN  1024
#define DPRJ 512
#define DOUT 1024
#define LORD 20
#define MROWS (B_ * T_)          // 32768

// ---------------------------------------------------------------------------
// Device scratch (allocation-free)
// ---------------------------------------------------------------------------
__device__ float g_x[(size_t)MROWS * DPRJ];                 // x fp32 (conv in, out_cache)
__device__ __nv_bfloat16 g_a1h[(size_t)MROWS * DIN];        // input split hi
__device__ __nv_bfloat16 g_a1l[(size_t)MROWS * DIN];        // input split lo
__device__ __nv_bfloat16 g_mh[(size_t)MROWS * DPRJ];        // m split hi
__device__ __nv_bfloat16 g_ml[(size_t)MROWS * DPRJ];        // m split lo
// Transposed, split weights: rows = N dim, K contiguous
__device__ __nv_bfloat16 g_b1h[(size_t)DPRJ * DIN];         // [512][1024]
__device__ __nv_bfloat16 g_b1l[(size_t)DPRJ * DIN];
__device__ __nv_bfloat16 g_b2h[(size_t)DOUT * DPRJ];        // [1024][512]
__device__ __nv_bfloat16 g_b2l[(size_t)DOUT * DPRJ];

__device__ __forceinline__ float4 ld4(const float* p) {
    return *reinterpret_cast<const float4*>(p);
}

__device__ __forceinline__ uint32_t smem_u32(const void* p) {
    uint32_t a;
    asm("{ .reg .u64 t; cvta.to.shared.u64 t, %1; cvt.u32.u64 %0, t; }"
        : "=r"(a) : "l"(p));
    return a;
}

// cp.async 16B global -> shared
__device__ __forceinline__ void cp16(uint32_t dst, const void* src) {
    asm volatile("cp.async.cg.shared.global [%0], [%1], 16;"
                 :: "r"(dst), "l"(src));
}
#define CP_COMMIT() asm volatile("cp.async.commit_group;" ::: "memory")
template <int N>
__device__ __forceinline__ void cp_wait() {
    asm volatile("cp.async.wait_group %0;" :: "n"(N) : "memory");
}

// ldmatrix x4 (four 8x8 b16 matrices)
__device__ __forceinline__ void ldsm4(uint32_t* r, uint32_t addr) {
    asm volatile("ldmatrix.sync.aligned.m8n8.x4.shared.b16 {%0,%1,%2,%3}, [%4];"
                 : "=r"(r[0]), "=r"(r[1]), "=r"(r[2]), "=r"(r[3])
                 : "r"(addr));
}

// mma.sync m16n8k16 bf16 -> f32
__device__ __forceinline__ void mma_bf16(float* c, const uint32_t* a,
                                         uint32_t b0, uint32_t b1) {
    asm volatile(
        "mma.sync.aligned.m16n8k16.row.col.f32.bf16.bf16.f32 "
        "{%0,%1,%2,%3}, {%4,%5,%6,%7}, {%8,%9}, {%0,%1,%2,%3};"
        : "+f"(c[0]), "+f"(c[1]), "+f"(c[2]), "+f"(c[3])
        : "r"(a[0]), "r"(a[1]), "r"(a[2]), "r"(a[3]), "r"(b0), "r"(b1));
}

// XOR-swizzled SMEM offset: rows of 32 bf16 (64B), 16B granules.
// swz(r, c16) with c16' = c16 ^ ((r>>1)&3): conflict-free for ldmatrix
// 8-row phases AND for cp.async warp-wide stores; all 16B aligned.
__device__ __forceinline__ uint32_t swz(uint32_t r, uint32_t c16) {
    return r * 64 + ((c16 ^ ((r >> 1) & 3)) << 4);
}

// ---------------------------------------------------------------------------
// Tensor-core GEMM via mma.sync: C[M,N] = A[M,K] * B^T (bf16 3-term split)
// All operands pre-split bf16 in GMEM. cp.async 3-stage pipeline, 2 CTAs/SM.
// CTA 128x128, KC=32, 256 threads (8 warps, 2x4), warp tile 64x32.
// SMEM stage: Ah, Al, Bh, Bl each [128][32] bf16, XOR-swizzled (no padding).
// ---------------------------------------------------------------------------
#define KC        32
#define TEN_BYTES (128 * 32 * 2)          // 8192
#define STG_BYTES (4 * TEN_BYTES)         // 32768
#define STAGES    3                       // 98304 B/CTA -> 2 CTAs/SM (196K <= 228K)

template <bool RELU>
__global__ __launch_bounds__(256, 2)
void gemm_mma(int M, int N, int K,
              const __nv_bfloat16* __restrict__ Ahg_,
              const __nv_bfloat16* __restrict__ Alg_,
              const __nv_bfloat16* __restrict__ Bhg_,
              const __nv_bfloat16* __restrict__ Blg_,
              const float* __restrict__ bias,
              float* __restrict__ C)
{
    extern __shared__ char smem_raw[];
    const uint32_t sb = smem_u32(smem_raw);

    const int tid  = threadIdx.x;
    const int lane = tid & 31;
    const int wid  = tid >> 5;
    const int warpM = wid >> 2;           // 0..1
    const int warpN = wid & 3;            // 0..3
    const int nt = blockIdx.x;
    const int mt = blockIdx.y;
    const int NKC = K / KC;

    const __nv_bfloat16* Ahg = Ahg_ + (size_t)mt * 128 * K;
    const __nv_bfloat16* Alg = Alg_ + (size_t)mt * 128 * K;
    const __nv_bfloat16* Bhg = Bhg_ + (size_t)nt * 128 * K;
    const __nv_bfloat16* Blg = Blg_ + (size_t)nt * 128 * K;

    float acc[4][4][4];
    #pragma unroll
    for (int i = 0; i < 4; i++)
        #pragma unroll
        for (int j = 0; j < 4; j++)
            #pragma unroll
            for (int q = 0; q < 4; q++) acc[i][j][q] = 0.f;

    // per-thread cp.async coordinates: 2 chunks of 16B per tensor
    const int r0 = tid >> 2,          c0 = tid & 3;
    const int r1 = (tid + 256) >> 2,  c1 = (tid + 256) & 3;
    const uint32_t so0 = swz((uint32_t)r0, (uint32_t)c0);
    const uint32_t so1 = swz((uint32_t)r1, (uint32_t)c1);

    auto issue = [&](int slot, int kc) {
        const uint32_t st = sb + slot * STG_BYTES;
        const size_t g0 = (size_t)r0 * K + kc * KC + c0 * 8;
        const size_t g1 = (size_t)r1 * K + kc * KC + c1 * 8;
        cp16(st + so0,                 Ahg + g0);
        cp16(st + so1,                 Ahg + g1);
        cp16(st + TEN_BYTES + so0,     Alg + g0);
        cp16(st + TEN_BYTES + so1,     Alg + g1);
        cp16(st + 2 * TEN_BYTES + so0, Bhg + g0);
        cp16(st + 2 * TEN_BYTES + so1, Bhg + g1);
        cp16(st + 3 * TEN_BYTES + so0, Blg + g0);
        cp16(st + 3 * TEN_BYTES + so1, Blg + g1);
        CP_COMMIT();
    };

    const int lr = lane & 15;
    const int lc = lane >> 4;

    auto compute = [&](int slot) {
        const uint32_t sAh = sb + slot * STG_BYTES;
        const uint32_t sAl = sAh + TEN_BYTES;
        const uint32_t sBh = sAh + 2 * TEN_BYTES;
        const uint32_t sBl = sAh + 3 * TEN_BYTES;
        #pragma unroll
        for (int ks = 0; ks < KC; ks += 16) {
            const uint32_t cbase = (uint32_t)(ks >> 3) + (uint32_t)lc;  // 16B col idx
            uint32_t ah[4][4], al[4][4], bh[2][4], bl[2][4];
            #pragma unroll
            for (int i = 0; i < 4; i++) {
                const uint32_t ao = swz((uint32_t)(warpM * 64 + i * 16 + lr), cbase);
                ldsm4(ah[i], sAh + ao);
                ldsm4(al[i], sAl + ao);
            }
            #pragma unroll
            for (int jj = 0; jj < 2; jj++) {
                const uint32_t bo = swz((uint32_t)(warpN * 32 + jj * 16 + lr), cbase);
                ldsm4(bh[jj], sBh + bo);
                ldsm4(bl[jj], sBl + bo);
            }
            #pragma unroll
            for (int i = 0; i < 4; i++) {
                #pragma unroll
                for (int j = 0; j < 4; j++) {
                    const int jj = j >> 1, sel = j & 1;
                    const uint32_t b0h = bh[jj][sel], b1h = bh[jj][sel + 2];
                    mma_bf16(acc[i][j], ah[i], b0h, b1h);                       // Ah*Bh
                    mma_bf16(acc[i][j], al[i], b0h, b1h);                       // Al*Bh
                    mma_bf16(acc[i][j], ah[i], bl[jj][sel], bl[jj][sel + 2]);   // Ah*Bl
                }
            }
        }
    };

    // ---- 3-stage cp.async pipeline, loads 2 chunks ahead ----
    // Iter kc: wait(group kc done, <=1 outstanding) -> sync -> issue(kc+2)
    //          -> compute(kc).
    // issue(kc+2) writes the slot compute(kc-1) used; the barrier this
    // iteration ordered all warps past compute(kc-1).
    issue(0, 0);
    issue(1, 1);
    for (int kc = 0; kc < NKC; kc++) {
        cp_wait<1>();
        __syncthreads();
        const int nk = kc + 2;
        if (nk < NKC) issue(nk % STAGES, nk);   // overlaps compute(kc)
        compute(kc % STAGES);
    }

    // ---- epilogue ----
    #pragma unroll
    for (int i = 0; i < 4; i++) {
        const int row0 = mt * 128 + warpM * 64 + i * 16 + (lane >> 2);
        #pragma unroll
        for (int j = 0; j < 4; j++) {
            const int col = nt * 128 + warpN * 32 + j * 8 + (lane & 3) * 2;
            float2 v0, v1;
            v0.x = acc[i][j][0]; v0.y = acc[i][j][1];   // row0
            v1.x = acc[i][j][2]; v1.y = acc[i][j][3];   // row0 + 8
            if (RELU) {
                const float b0 = bias[col], b1 = bias[col + 1];
                v0.x = fmaxf(v0.x + b0, 0.f); v0.y = fmaxf(v0.y + b1, 0.f);
                v1.x = fmaxf(v1.x + b0, 0.f); v1.y = fmaxf(v1.y + b1, 0.f);
            }
            *reinterpret_cast<float2*>(C + (size_t)row0 * N + col)       = v0;
            *reinterpret_cast<float2*>(C + (size_t)(row0 + 8) * N + col) = v1;
        }
    }
}

// ---------------------------------------------------------------------------
// Input pre-split: fp32 -> bf16 hi/lo (vectorized)
// ---------------------------------------------------------------------------
__global__ void split_input(const float* __restrict__ in,
                            __nv_bfloat16* __restrict__ h,
                            __nv_bfloat16* __restrict__ l)
{
    const size_t i4 = (size_t)blockIdx.x * 256 + threadIdx.x;  // float4 index
    const float4 v = ld4(in + i4 * 4);
    __nv_bfloat16 hx = __float2bfloat16(v.x);
    __nv_bfloat16 hy = __float2bfloat16(v.y);
    __nv_bfloat16 hz = __float2bfloat16(v.z);
    __nv_bfloat16 hw = __float2bfloat16(v.w);
    __nv_bfloat16 lx = __float2bfloat16(v.x - __bfloat162float(hx));
    __nv_bfloat16 ly = __float2bfloat16(v.y - __bfloat162float(hy));
    __nv_bfloat16 lz = __float2bfloat16(v.z - __bfloat162float(hz));
    __nv_bfloat16 lw = __float2bfloat16(v.w - __bfloat162float(hw));
    uint2 hv, lv;
    hv.x = (uint32_t)__bfloat16_as_ushort(hx) | ((uint32_t)__bfloat16_as_ushort(hy) << 16);
    hv.y = (uint32_t)__bfloat16_as_ushort(hz) | ((uint32_t)__bfloat16_as_ushort(hw) << 16);
    lv.x = (uint32_t)__bfloat16_as_ushort(lx) | ((uint32_t)__bfloat16_as_ushort(ly) << 16);
    lv.y = (uint32_t)__bfloat16_as_ushort(lz) | ((uint32_t)__bfloat16_as_ushort(lw) << 16);
    *reinterpret_cast<uint2*>(h + i4 * 4) = hv;
    *reinterpret_cast<uint2*>(l + i4 * 4) = lv;
}

// ---------------------------------------------------------------------------
// Weight prep: transpose + bf16 hi/lo split
// ---------------------------------------------------------------------------
__global__ void prep_w1(const float* __restrict__ W,   // W_lin [1024,512]
                        __nv_bfloat16* __restrict__ bh,
                        __nv_bfloat16* __restrict__ bl)
{
    const int idx = blockIdx.x * 256 + threadIdx.x;
    if (idx >= DPRJ * DIN) return;
    const int n = idx / DIN, k = idx % DIN;
    const float v = W[(size_t)k * DPRJ + n];
    const __nv_bfloat16 h = __float2bfloat16(v);
    bh[idx] = h;
    bl[idx] = __float2bfloat16(v - __bfloat162float(h));
}

__global__ void prep_w2(const float* __restrict__ W,   // W_aff [512,1024]
                        __nv_bfloat16* __restrict__ bh,
                        __nv_bfloat16* __restrict__ bl)
{
    const int idx = blockIdx.x * 256 + threadIdx.x;
    if (idx >= DOUT * DPRJ) return;
    const int o = idx / DPRJ, p = idx % DPRJ;
    const float v = W[(size_t)p * DOUT + o];
    const __nv_bfloat16 h = __float2bfloat16(v);
    bh[idx] = h;
    bl[idx] = __float2bfloat16(v - __bfloat162float(h));
}

// ---------------------------------------------------------------------------
// Depthwise causal conv (L=20) + residual; emits m as bf16 hi/lo directly
// ---------------------------------------------------------------------------
#define TCHUNK 128

__global__ __launch_bounds__(256)
void conv_residual_kernel(const float* __restrict__ x,
                          const float* __restrict__ in_cache,
                          const float* __restrict__ conv_w,
                          __nv_bfloat16* __restrict__ mh,
                          __nv_bfloat16* __restrict__ ml)
{
    const int p  = blockIdx.x * 256 + threadIdx.x;
    const int b  = blockIdx.z;
    const int t0 = blockIdx.y * TCHUNK;

    float w[LORD];
    #pragma unroll
    for (int l = 0; l < LORD; l++) w[l] = conv_w[p * LORD + l];

    float win[LORD - 1];
    #pragma unroll
    for (int i = 0; i < LORD - 1; i++) {
        const int j = t0 - (LORD - 1) + i;
        if (j >= 0)
            win[i] = x[((size_t)b * T_ + j) * DPRJ + p];
        else
            win[i] = in_cache[((size_t)b * DPRJ + p) * (LORD - 1) + (j + LORD - 1)];
    }

    const float* xrow = x  + ((size_t)b * T_ + t0) * DPRJ + p;
    __nv_bfloat16* mhrow = mh + ((size_t)b * T_ + t0) * DPRJ + p;
    __nv_bfloat16* mlrow = ml + ((size_t)b * T_ + t0) * DPRJ + p;

    for (int t = 0; t < TCHUNK; t++) {
        const float xv = xrow[(size_t)t * DPRJ];
        float acc = fmaf(w[LORD - 1], xv, xv);
        #pragma unroll
        for (int l = 0; l < LORD - 1; l++)
            acc = fmaf(w[l], win[l], acc);
        const __nv_bfloat16 h = __float2bfloat16(acc);
        mhrow[(size_t)t * DPRJ] = h;
        mlrow[(size_t)t * DPRJ] = __float2bfloat16(acc - __bfloat162float(h));
        #pragma unroll
        for (int i = 0; i < LORD - 2; i++) win[i] = win[i + 1];
        win[LORD - 2] = xv;
    }
}

__global__ void cache_kernel(const float* __restrict__ x,
                             float* __restrict__ out_cache)
{
    const int idx = blockIdx.x * blockDim.x + threadIdx.x;
    const int total = B_ * DPRJ * (LORD - 1);
    if (idx >= total) return;
    const int i = idx % (LORD - 1);
    const int p = (idx / (LORD - 1)) % DPRJ;
    const int b = idx / ((LORD - 1) * DPRJ);
    out_cache[idx] = x[((size_t)b * T_ + (T_ - (LORD - 1) + i)) * DPRJ + p];
}

// ---------------------------------------------------------------------------
extern "C" void kernel_launch(void* const* d_in, const int* in_sizes, int n_in,
                              void* d_out, int out_size)
{
    const float* input    = (const float*)d_in[0];  // [16, 2048, 1024]
    const float* in_cache = (const float*)d_in[1];  // [16, 512, 19]
    const float* W_lin    = (const float*)d_in[2];  // [1024, 512]
    const float* conv_w   = (const float*)d_in[3];  // [512, 20]
    const float* W_aff    = (const float*)d_in[4];  // [512, 1024]
    const float* b_aff    = (const float*)d_in[5];  // [1024]

    float* out       = (float*)d_out;
    float* out_cache = out + (size_t)B_ * T_ * DOUT;

    float *xbuf;
    __nv_bfloat16 *a1h, *a1l, *mh, *ml, *b1h, *b1l, *b2h, *b2l;
    cudaGetSymbolAddress((void**)&xbuf, g_x);
    cudaGetSymbolAddress((void**)&a1h, g_a1h);
    cudaGetSymbolAddress((void**)&a1l, g_a1l);
    cudaGetSymbolAddress((void**)&mh,  g_mh);
    cudaGetSymbolAddress((void**)&ml,  g_ml);
    cudaGetSymbolAddress((void**)&b1h, g_b1h);
    cudaGetSymbolAddress((void**)&b1l, g_b1l);
    cudaGetSymbolAddress((void**)&b2h, g_b2h);
    cudaGetSymbolAddress((void**)&b2l, g_b2l);

    const int SMEM_SZ = STAGES * STG_BYTES;   // 98304 B -> 2 CTAs/SM
    cudaFuncSetAttribute(gemm_mma<false>, cudaFuncAttributeMaxDynamicSharedMemorySize, SMEM_SZ);
    cudaFuncSetAttribute(gemm_mma<true>,  cudaFuncAttributeMaxDynamicSharedMemorySize, SMEM_SZ);

    // 0) operand prep: input split + weight transpose/split
    split_input<<<(MROWS * (size_t)DIN / 4 + 255) / 256, 256>>>(input, a1h, a1l);
    prep_w1<<<(DPRJ * DIN + 255) / 256, 256>>>(W_lin, b1h, b1l);
    prep_w2<<<(DOUT * DPRJ + 255) / 256, 256>>>(W_aff, b2h, b2l);

    // 1) x = input @ W_lin      M=32768, N=512, K=1024
    {
        dim3 grid(DPRJ / 128, MROWS / 128);
        gemm_mma<false><<<grid, 256, SMEM_SZ>>>(MROWS, DPRJ, DIN,
                                                a1h, a1l, b1h, b1l, nullptr, xbuf);
    }

    // 2) m = depthwise_conv(x) + x  (bf16 split out) ; out_cache
    {
        dim3 grid(DPRJ / 256, T_ / TCHUNK, B_);
        conv_residual_kernel<<<grid, 256>>>(xbuf, in_cache, conv_w, mh, ml);
        const int total = B_ * DPRJ * (LORD - 1);
        cache_kernel<<<(total + 255) / 256, 256>>>(xbuf, out_cache);
    }

    // 3) out = relu(m @ W_aff + b_aff)   M=32768, N=1024, K=512
    {
        dim3 grid(DOUT / 128, MROWS / 128);
        gemm_mma<true><<<grid, 256, SMEM_SZ>>>(MROWS, DOUT, DPRJ,
                                               mh, ml, b2h, b2l, b_aff, out);
    }
}

// round 15
// speedup vs baseline: 1.2880x; 1.0223x over previous
#include <cuda_runtime.h>
#include <cuda_bf16.h>
#include <cstdint>

// Problem constants
#define B_   16
#define T_   2048
#define DIN  1024
#define DPRJ 512
#define DOUT 1024
#define LORD 20
#define MROWS (B_ * T_)          // 32768

// ---------------------------------------------------------------------------
// Device scratch (allocation-free)
// ---------------------------------------------------------------------------
__device__ float g_x[(size_t)MROWS * DPRJ];                 // x fp32 (conv in, out_cache)
__device__ __nv_bfloat16 g_a1h[(size_t)MROWS * DIN];        // input split hi
__device__ __nv_bfloat16 g_a1l[(size_t)MROWS * DIN];        // input split lo
__device__ __nv_bfloat16 g_mh[(size_t)MROWS * DPRJ];        // m split hi
__device__ __nv_bfloat16 g_ml[(size_t)MROWS * DPRJ];        // m split lo
// Transposed, split weights: rows = N dim, K contiguous
__device__ __nv_bfloat16 g_b1h[(size_t)DPRJ * DIN];         // [512][1024]
__device__ __nv_bfloat16 g_b1l[(size_t)DPRJ * DIN];
__device__ __nv_bfloat16 g_b2h[(size_t)DOUT * DPRJ];        // [1024][512]
__device__ __nv_bfloat16 g_b2l[(size_t)DOUT * DPRJ];

__device__ __forceinline__ float4 ld4(const float* p) {
    return *reinterpret_cast<const float4*>(p);
}

__device__ __forceinline__ uint32_t smem_u32(const void* p) {
    uint32_t a;
    asm("{ .reg .u64 t; cvta.to.shared.u64 t, %1; cvt.u32.u64 %0, t; }"
        : "=r"(a) : "l"(p));
    return a;
}

// cp.async 16B global -> shared
__device__ __forceinline__ void cp16(uint32_t dst, const void* src) {
    asm volatile("cp.async.cg.shared.global [%0], [%1], 16;"
                 :: "r"(dst), "l"(src));
}
#define CP_COMMIT() asm volatile("cp.async.commit_group;" ::: "memory")
template <int N>
__device__ __forceinline__ void cp_wait() {
    asm volatile("cp.async.wait_group %0;" :: "n"(N) : "memory");
}

// ldmatrix x4 (four 8x8 b16 matrices)
__device__ __forceinline__ void ldsm4(uint32_t* r, uint32_t addr) {
    asm volatile("ldmatrix.sync.aligned.m8n8.x4.shared.b16 {%0,%1,%2,%3}, [%4];"
                 : "=r"(r[0]), "=r"(r[1]), "=r"(r[2]), "=r"(r[3])
                 : "r"(addr));
}

// mma.sync m16n8k16 bf16 -> f32
__device__ __forceinline__ void mma_bf16(float* c, const uint32_t* a,
                                         uint32_t b0, uint32_t b1) {
    asm volatile(
        "mma.sync.aligned.m16n8k16.row.col.f32.bf16.bf16.f32 "
        "{%0,%1,%2,%3}, {%4,%5,%6,%7}, {%8,%9}, {%0,%1,%2,%3};"
        : "+f"(c[0]), "+f"(c[1]), "+f"(c[2]), "+f"(c[3])
        : "r"(a[0]), "r"(a[1]), "r"(a[2]), "r"(a[3]), "r"(b0), "r"(b1));
}

// XOR-swizzled SMEM offset: rows of 32 bf16 (64B), 16B granules.
// swz(r, c16) with c16' = c16 ^ ((r>>1)&3): conflict-free for ldmatrix
// 8-row phases AND for cp.async warp-wide stores; all 16B aligned.
// Identity used in the mainloop: swz(r, c+2) == swz(r, c) ^ 32.
__device__ __forceinline__ uint32_t swz(uint32_t r, uint32_t c16) {
    return r * 64 + ((c16 ^ ((r >> 1) & 3)) << 4);
}

// ---------------------------------------------------------------------------
// Tensor-core GEMM via mma.sync: C[M,N] = A[M,K] * B^T (bf16 3-term split)
// All operands pre-split bf16 in GMEM. cp.async 3-stage pipeline, 2 CTAs/SM.
// CTA 128x128, KC=32, 256 threads (8 warps, 2x4), warp tile 64x32.
// SMEM stage: Ah, Al, Bh, Bl each [128][32] bf16, XOR-swizzled (no padding).
// Mainloop ALU minimized: ldmatrix offsets hoisted to registers (second
// k-step = offset ^ 32), global pointers advanced incrementally.
// ---------------------------------------------------------------------------
#define KC        32
#define TEN_BYTES (128 * 32 * 2)          // 8192
#define STG_BYTES (4 * TEN_BYTES)         // 32768
#define STAGES    3                       // 98304 B/CTA -> 2 CTAs/SM

template <bool RELU>
__global__ __launch_bounds__(256, 2)
void gemm_mma(int M, int N, int K,
              const __nv_bfloat16* __restrict__ Ahg_,
              const __nv_bfloat16* __restrict__ Alg_,
              const __nv_bfloat16* __restrict__ Bhg_,
              const __nv_bfloat16* __restrict__ Blg_,
              const float* __restrict__ bias,
              float* __restrict__ C)
{
    extern __shared__ char smem_raw[];
    const uint32_t sb = smem_u32(smem_raw);

    const int tid  = threadIdx.x;
    const int lane = tid & 31;
    const int wid  = tid >> 5;
    const int warpM = wid >> 2;           // 0..1
    const int warpN = wid & 3;            // 0..3
    const int nt = blockIdx.x;
    const int mt = blockIdx.y;
    const int NKC = K / KC;

    float acc[4][4][4];
    #pragma unroll
    for (int i = 0; i < 4; i++)
        #pragma unroll
        for (int j = 0; j < 4; j++)
            #pragma unroll
            for (int q = 0; q < 4; q++) acc[i][j][q] = 0.f;

    // ---- per-thread cp.async coordinates: 2 chunks of 16B per tensor ----
    const int r0 = tid >> 2,          c0 = tid & 3;
    const int r1 = (tid + 256) >> 2,  c1 = (tid + 256) & 3;
    const uint32_t so0 = swz((uint32_t)r0, (uint32_t)c0);
    const uint32_t so1 = swz((uint32_t)r1, (uint32_t)c1);

    // incremental global pointers (advance by KC per issued chunk)
    const __nv_bfloat16* pAh0 = Ahg_ + (size_t)(mt * 128 + r0) * K + c0 * 8;
    const __nv_bfloat16* pAh1 = Ahg_ + (size_t)(mt * 128 + r1) * K + c1 * 8;
    const __nv_bfloat16* pAl0 = Alg_ + (size_t)(mt * 128 + r0) * K + c0 * 8;
    const __nv_bfloat16* pAl1 = Alg_ + (size_t)(mt * 128 + r1) * K + c1 * 8;
    const __nv_bfloat16* pBh0 = Bhg_ + (size_t)(nt * 128 + r0) * K + c0 * 8;
    const __nv_bfloat16* pBh1 = Bhg_ + (size_t)(nt * 128 + r1) * K + c1 * 8;
    const __nv_bfloat16* pBl0 = Blg_ + (size_t)(nt * 128 + r0) * K + c0 * 8;
    const __nv_bfloat16* pBl1 = Blg_ + (size_t)(nt * 128 + r1) * K + c1 * 8;

    auto issue = [&](int slot) {
        const uint32_t st = sb + slot * STG_BYTES;
        cp16(st + so0,                 pAh0);
        cp16(st + so1,                 pAh1);
        cp16(st + TEN_BYTES + so0,     pAl0);
        cp16(st + TEN_BYTES + so1,     pAl1);
        cp16(st + 2 * TEN_BYTES + so0, pBh0);
        cp16(st + 2 * TEN_BYTES + so1, pBh1);
        cp16(st + 3 * TEN_BYTES + so0, pBl0);
        cp16(st + 3 * TEN_BYTES + so1, pBl1);
        CP_COMMIT();
        pAh0 += KC; pAh1 += KC; pAl0 += KC; pAl1 += KC;
        pBh0 += KC; pBh1 += KC; pBl0 += KC; pBl1 += KC;
    };

    // ---- hoisted ldmatrix offsets (ks=0); second k-step = offset ^ 32 ----
    const int lr = lane & 15;
    const int lc = lane >> 4;
    uint32_t aoff[4], boff[2];
    #pragma unroll
    for (int i = 0; i < 4; i++)
        aoff[i] = swz((uint32_t)(warpM * 64 + i * 16 + lr), (uint32_t)lc);
    #pragma unroll
    for (int jj = 0; jj < 2; jj++)
        boff[jj] = swz((uint32_t)(warpN * 32 + jj * 16 + lr), (uint32_t)lc);

    auto compute = [&](int slot) {
        const uint32_t sAh = sb + slot * STG_BYTES;
        const uint32_t sAl = sAh + TEN_BYTES;
        const uint32_t sBh = sAh + 2 * TEN_BYTES;
        const uint32_t sBl = sAh + 3 * TEN_BYTES;
        #pragma unroll
        for (int ks = 0; ks < 2; ks++) {
            const uint32_t kx = ks ? 32u : 0u;
            uint32_t ah[4][4], al[4][4], bh[2][4], bl[2][4];
            #pragma unroll
            for (int i = 0; i < 4; i++) {
                const uint32_t ao = aoff[i] ^ kx;
                ldsm4(ah[i], sAh + ao);
                ldsm4(al[i], sAl + ao);
            }
            #pragma unroll
            for (int jj = 0; jj < 2; jj++) {
                const uint32_t bo = boff[jj] ^ kx;
                ldsm4(bh[jj], sBh + bo);
                ldsm4(bl[jj], sBl + bo);
            }
            #pragma unroll
            for (int i = 0; i < 4; i++) {
                #pragma unroll
                for (int j = 0; j < 4; j++) {
                    const int jj = j >> 1, sel = j & 1;
                    const uint32_t b0h = bh[jj][sel], b1h = bh[jj][sel + 2];
                    mma_bf16(acc[i][j], ah[i], b0h, b1h);                       // Ah*Bh
                    mma_bf16(acc[i][j], al[i], b0h, b1h);                       // Al*Bh
                    mma_bf16(acc[i][j], ah[i], bl[jj][sel], bl[jj][sel + 2]);   // Ah*Bl
                }
            }
        }
    };

    // ---- 3-stage cp.async pipeline, loads 2 chunks ahead ----
    // Iter kc: wait(group kc, <=1 outstanding) -> sync -> issue(kc+2)
    //          -> compute(kc).  (Only race-free order at 3 stages.)
    issue(0);
    issue(1);
    for (int kc = 0; kc < NKC; kc++) {
        cp_wait<1>();
        __syncthreads();
        if (kc + 2 < NKC) issue((kc + 2) % STAGES);   // overlaps compute(kc)
        compute(kc % STAGES);
    }

    // ---- epilogue ----
    #pragma unroll
    for (int i = 0; i < 4; i++) {
        const int row0 = mt * 128 + warpM * 64 + i * 16 + (lane >> 2);
        #pragma unroll
        for (int j = 0; j < 4; j++) {
            const int col = nt * 128 + warpN * 32 + j * 8 + (lane & 3) * 2;
            float2 v0, v1;
            v0.x = acc[i][j][0]; v0.y = acc[i][j][1];   // row0
            v1.x = acc[i][j][2]; v1.y = acc[i][j][3];   // row0 + 8
            if (RELU) {
                const float b0 = bias[col], b1 = bias[col + 1];
                v0.x = fmaxf(v0.x + b0, 0.f); v0.y = fmaxf(v0.y + b1, 0.f);
                v1.x = fmaxf(v1.x + b0, 0.f); v1.y = fmaxf(v1.y + b1, 0.f);
            }
            *reinterpret_cast<float2*>(C + (size_t)row0 * N + col)       = v0;
            *reinterpret_cast<float2*>(C + (size_t)(row0 + 8) * N + col) = v1;
        }
    }
}

// ---------------------------------------------------------------------------
// Input pre-split: fp32 -> bf16 hi/lo (vectorized)
// ---------------------------------------------------------------------------
__global__ void split_input(const float* __restrict__ in,
                            __nv_bfloat16* __restrict__ h,
                            __nv_bfloat16* __restrict__ l)
{
    const size_t i4 = (size_t)blockIdx.x * 256 + threadIdx.x;  // float4 index
    const float4 v = ld4(in + i4 * 4);
    __nv_bfloat16 hx = __float2bfloat16(v.x);
    __nv_bfloat16 hy = __float2bfloat16(v.y);
    __nv_bfloat16 hz = __float2bfloat16(v.z);
    __nv_bfloat16 hw = __float2bfloat16(v.w);
    __nv_bfloat16 lx = __float2bfloat16(v.x - __bfloat162float(hx));
    __nv_bfloat16 ly = __float2bfloat16(v.y - __bfloat162float(hy));
    __nv_bfloat16 lz = __float2bfloat16(v.z - __bfloat162float(hz));
    __nv_bfloat16 lw = __float2bfloat16(v.w - __bfloat162float(hw));
    uint2 hv, lv;
    hv.x = (uint32_t)__bfloat16_as_ushort(hx) | ((uint32_t)__bfloat16_as_ushort(hy) << 16);
    hv.y = (uint32_t)__bfloat16_as_ushort(hz) | ((uint32_t)__bfloat16_as_ushort(hw) << 16);
    lv.x = (uint32_t)__bfloat16_as_ushort(lx) | ((uint32_t)__bfloat16_as_ushort(ly) << 16);
    lv.y = (uint32_t)__bfloat16_as_ushort(lz) | ((uint32_t)__bfloat16_as_ushort(lw) << 16);
    *reinterpret_cast<uint2*>(h + i4 * 4) = hv;
    *reinterpret_cast<uint2*>(l + i4 * 4) = lv;
}

// ---------------------------------------------------------------------------
// Weight prep: transpose + bf16 hi/lo split
// ---------------------------------------------------------------------------
__global__ void prep_w1(const float* __restrict__ W,   // W_lin [1024,512]
                        __nv_bfloat16* __restrict__ bh,
                        __nv_bfloat16* __restrict__ bl)
{
    const int idx = blockIdx.x * 256 + threadIdx.x;
    if (idx >= DPRJ * DIN) return;
    const int n = idx / DIN, k = idx % DIN;
    const float v = W[(size_t)k * DPRJ + n];
    const __nv_bfloat16 h = __float2bfloat16(v);
    bh[idx] = h;
    bl[idx] = __float2bfloat16(v - __bfloat162float(h));
}

__global__ void prep_w2(const float* __restrict__ W,   // W_aff [512,1024]
                        __nv_bfloat16* __restrict__ bh,
                        __nv_bfloat16* __restrict__ bl)
{
    const int idx = blockIdx.x * 256 + threadIdx.x;
    if (idx >= DOUT * DPRJ) return;
    const int o = idx / DPRJ, p = idx % DPRJ;
    const float v = W[(size_t)p * DOUT + o];
    const __nv_bfloat16 h = __float2bfloat16(v);
    bh[idx] = h;
    bl[idx] = __float2bfloat16(v - __bfloat162float(h));
}

// ---------------------------------------------------------------------------
// Depthwise causal conv (L=20) + residual; emits m as bf16 hi/lo directly
// ---------------------------------------------------------------------------
#define TCHUNK 128

__global__ __launch_bounds__(256)
void conv_residual_kernel(const float* __restrict__ x,
                          const float* __restrict__ in_cache,
                          const float* __restrict__ conv_w,
                          __nv_bfloat16* __restrict__ mh,
                          __nv_bfloat16* __restrict__ ml)
{
    const int p  = blockIdx.x * 256 + threadIdx.x;
    const int b  = blockIdx.z;
    const int t0 = blockIdx.y * TCHUNK;

    float w[LORD];
    #pragma unroll
    for (int l = 0; l < LORD; l++) w[l] = conv_w[p * LORD + l];

    float win[LORD - 1];
    #pragma unroll
    for (int i = 0; i < LORD - 1; i++) {
        const int j = t0 - (LORD - 1) + i;
        if (j >= 0)
            win[i] = x[((size_t)b * T_ + j) * DPRJ + p];
        else
            win[i] = in_cache[((size_t)b * DPRJ + p) * (LORD - 1) + (j + LORD - 1)];
    }

    const float* xrow = x  + ((size_t)b * T_ + t0) * DPRJ + p;
    __nv_bfloat16* mhrow = mh + ((size_t)b * T_ + t0) * DPRJ + p;
    __nv_bfloat16* mlrow = ml + ((size_t)b * T_ + t0) * DPRJ + p;

    for (int t = 0; t < TCHUNK; t++) {
        const float xv = xrow[(size_t)t * DPRJ];
        float acc = fmaf(w[LORD - 1], xv, xv);
        #pragma unroll
        for (int l = 0; l < LORD - 1; l++)
            acc = fmaf(w[l], win[l], acc);
        const __nv_bfloat16 h = __float2bfloat16(acc);
        mhrow[(size_t)t * DPRJ] = h;
        mlrow[(size_t)t * DPRJ] = __float2bfloat16(acc - __bfloat162float(h));
        #pragma unroll
        for (int i = 0; i < LORD - 2; i++) win[i] = win[i + 1];
        win[LORD - 2] = xv;
    }
}

__global__ void cache_kernel(const float* __restrict__ x,
                             float* __restrict__ out_cache)
{
    const int idx = blockIdx.x * blockDim.x + threadIdx.x;
    const int total = B_ * DPRJ * (LORD - 1);
    if (idx >= total) return;
    const int i = idx % (LORD - 1);
    const int p = (idx / (LORD - 1)) % DPRJ;
    const int b = idx / ((LORD - 1) * DPRJ);
    out_cache[idx] = x[((size_t)b * T_ + (T_ - (LORD - 1) + i)) * DPRJ + p];
}

// ---------------------------------------------------------------------------
extern "C" void kernel_launch(void* const* d_in, const int* in_sizes, int n_in,
                              void* d_out, int out_size)
{
    const float* input    = (const float*)d_in[0];  // [16, 2048, 1024]
    const float* in_cache = (const float*)d_in[1];  // [16, 512, 19]
    const float* W_lin    = (const float*)d_in[2];  // [1024, 512]
    const float* conv_w   = (const float*)d_in[3];  // [512, 20]
    const float* W_aff    = (const float*)d_in[4];  // [512, 1024]
    const float* b_aff    = (const float*)d_in[5];  // [1024]

    float* out       = (float*)d_out;
    float* out_cache = out + (size_t)B_ * T_ * DOUT;

    float *xbuf;
    __nv_bfloat16 *a1h, *a1l, *mh, *ml, *b1h, *b1l, *b2h, *b2l;
    cudaGetSymbolAddress((void**)&xbuf, g_x);
    cudaGetSymbolAddress((void**)&a1h, g_a1h);
    cudaGetSymbolAddress((void**)&a1l, g_a1l);
    cudaGetSymbolAddress((void**)&mh,  g_mh);
    cudaGetSymbolAddress((void**)&ml,  g_ml);
    cudaGetSymbolAddress((void**)&b1h, g_b1h);
    cudaGetSymbolAddress((void**)&b1l, g_b1l);
    cudaGetSymbolAddress((void**)&b2h, g_b2h);
    cudaGetSymbolAddress((void**)&b2l, g_b2l);

    const int SMEM_SZ = STAGES * STG_BYTES;   // 98304 B -> 2 CTAs/SM
    cudaFuncSetAttribute(gemm_mma<false>, cudaFuncAttributeMaxDynamicSharedMemorySize, SMEM_SZ);
    cudaFuncSetAttribute(gemm_mma<true>,  cudaFuncAttributeMaxDynamicSharedMemorySize, SMEM_SZ);

    // 0) operand prep: input split + weight transpose/split
    split_input<<<(MROWS * (size_t)DIN / 4 + 255) / 256, 256>>>(input, a1h, a1l);
    prep_w1<<<(DPRJ * DIN + 255) / 256, 256>>>(W_lin, b1h, b1l);
    prep_w2<<<(DOUT * DPRJ + 255) / 256, 256>>>(W_aff, b2h, b2l);

    // 1) x = input @ W_lin      M=32768, N=512, K=1024
    {
        dim3 grid(DPRJ / 128, MROWS / 128);
        gemm_mma<false><<<grid, 256, SMEM_SZ>>>(MROWS, DPRJ, DIN,
                                                a1h, a1l, b1h, b1l, nullptr, xbuf);
    }

    // 2) m = depthwise_conv(x) + x  (bf16 split out) ; out_cache
    {
        dim3 grid(DPRJ / 256, T_ / TCHUNK, B_);
        conv_residual_kernel<<<grid, 256>>>(xbuf, in_cache, conv_w, mh, ml);
        const int total = B_ * DPRJ * (LORD - 1);
        cache_kernel<<<(total + 255) / 256, 256>>>(xbuf, out_cache);
    }

    // 3) out = relu(m @ W_aff + b_aff)   M=32768, N=1024, K=512
    {
        dim3 grid(DOUT / 128, MROWS / 128);
        gemm_mma<true><<<grid, 256, SMEM_SZ>>>(MROWS, DOUT, DPRJ,
                                               mh, ml, b2h, b2l, b_aff, out);
    }
}

// round 16
// speedup vs baseline: 1.6726x; 1.2986x over previous
#include <cuda_runtime.h>
#include <cuda_fp16.h>
#include <cstdint>

// Problem constants
#define B_   16
#define T_   2048
#define DIN  1024
#define DPRJ 512
#define DOUT 1024
#define LORD 20
#define MROWS (B_ * T_)          // 32768

// ---------------------------------------------------------------------------
// Device scratch (allocation-free)
// ---------------------------------------------------------------------------
__device__ float g_x[(size_t)MROWS * DPRJ];          // x fp32 (conv in, out_cache)
__device__ __half g_a1h[(size_t)MROWS * DIN];        // input split hi (fp16)
__device__ __half g_a1l[(size_t)MROWS * DIN];        // input split lo (fp16)
__device__ __half g_mh[(size_t)MROWS * DPRJ];        // m split hi
__device__ __half g_ml[(size_t)MROWS * DPRJ];        // m split lo
// Transposed weights, single fp16: rows = N dim, K contiguous
__device__ __half g_b1[(size_t)DPRJ * DIN];          // [512][1024]
__device__ __half g_b2[(size_t)DOUT * DPRJ];         // [1024][512]

__device__ __forceinline__ float4 ld4(const float* p) {
    return *reinterpret_cast<const float4*>(p);
}

__device__ __forceinline__ uint32_t smem_u32(const void* p) {
    uint32_t a;
    asm("{ .reg .u64 t; cvta.to.shared.u64 t, %1; cvt.u32.u64 %0, t; }"
        : "=r"(a) : "l"(p));
    return a;
}

// cp.async 16B global -> shared
__device__ __forceinline__ void cp16(uint32_t dst, const void* src) {
    asm volatile("cp.async.cg.shared.global [%0], [%1], 16;"
                 :: "r"(dst), "l"(src));
}
#define CP_COMMIT() asm volatile("cp.async.commit_group;" ::: "memory")
template <int N>
__device__ __forceinline__ void cp_wait() {
    asm volatile("cp.async.wait_group %0;" :: "n"(N) : "memory");
}

// ldmatrix x4 (four 8x8 b16 matrices)
__device__ __forceinline__ void ldsm4(uint32_t* r, uint32_t addr) {
    asm volatile("ldmatrix.sync.aligned.m8n8.x4.shared.b16 {%0,%1,%2,%3}, [%4];"
                 : "=r"(r[0]), "=r"(r[1]), "=r"(r[2]), "=r"(r[3])
                 : "r"(addr));
}

// mma.sync m16n8k16 fp16 -> f32
__device__ __forceinline__ void mma_f16(float* c, const uint32_t* a,
                                        uint32_t b0, uint32_t b1) {
    asm volatile(
        "mma.sync.aligned.m16n8k16.row.col.f32.f16.f16.f32 "
        "{%0,%1,%2,%3}, {%4,%5,%6,%7}, {%8,%9}, {%0,%1,%2,%3};"
        : "+f"(c[0]), "+f"(c[1]), "+f"(c[2]), "+f"(c[3])
        : "r"(a[0]), "r"(a[1]), "r"(a[2]), "r"(a[3]), "r"(b0), "r"(b1));
}

// XOR-swizzled SMEM offset: rows of 32 halfs (64B), 16B granules.
// Conflict-free for ldmatrix 8-row phases and cp.async warp stores.
// Identity: swz(r, c+2) == swz(r, c) ^ 32.
__device__ __forceinline__ uint32_t swz(uint32_t r, uint32_t c16) {
    return r * 64 + ((c16 ^ ((r >> 1) & 3)) << 4);
}

// ---------------------------------------------------------------------------
// Tensor-core GEMM via mma.sync: C[M,N] = A[M,K] * B^T
// 2-term fp16 split: A = Ah + Al (fp16 pair), B single fp16; fp32 accum.
// cp.async 4-stage pipeline (loads 3 chunks ahead), 2 CTAs/SM.
// CTA 128x128, KC=32, 256 threads (8 warps, 2x4), warp tile 64x32.
// SMEM stage: Ah, Al, B each [128][32] fp16, XOR-swizzled.
// ---------------------------------------------------------------------------
#define KC        32
#define TEN_BYTES (128 * 32 * 2)          // 8192
#define STG_BYTES (3 * TEN_BYTES)         // 24576
#define STAGES    4                       // 98304 B/CTA -> 2 CTAs/SM

template <bool RELU>
__global__ __launch_bounds__(256, 2)
void gemm_mma(int M, int N, int K,
              const __half* __restrict__ Ahg_,
              const __half* __restrict__ Alg_,
              const __half* __restrict__ Bg_,
              const float* __restrict__ bias,
              float* __restrict__ C)
{
    extern __shared__ char smem_raw[];
    const uint32_t sb = smem_u32(smem_raw);

    const int tid  = threadIdx.x;
    const int lane = tid & 31;
    const int wid  = tid >> 5;
    const int warpM = wid >> 2;           // 0..1
    const int warpN = wid & 3;            // 0..3
    const int nt = blockIdx.x;
    const int mt = blockIdx.y;
    const int NKC = K / KC;

    float acc[4][4][4];
    #pragma unroll
    for (int i = 0; i < 4; i++)
        #pragma unroll
        for (int j = 0; j < 4; j++)
            #pragma unroll
            for (int q = 0; q < 4; q++) acc[i][j][q] = 0.f;

    // ---- per-thread cp.async coordinates: 2 chunks of 16B per tensor ----
    const int r0 = tid >> 2,          c0 = tid & 3;
    const int r1 = (tid + 256) >> 2,  c1 = (tid + 256) & 3;
    const uint32_t so0 = swz((uint32_t)r0, (uint32_t)c0);
    const uint32_t so1 = swz((uint32_t)r1, (uint32_t)c1);

    // incremental global pointers (advance by KC per issued chunk)
    const __half* pAh0 = Ahg_ + (size_t)(mt * 128 + r0) * K + c0 * 8;
    const __half* pAh1 = Ahg_ + (size_t)(mt * 128 + r1) * K + c1 * 8;
    const __half* pAl0 = Alg_ + (size_t)(mt * 128 + r0) * K + c0 * 8;
    const __half* pAl1 = Alg_ + (size_t)(mt * 128 + r1) * K + c1 * 8;
    const __half* pB0  = Bg_  + (size_t)(nt * 128 + r0) * K + c0 * 8;
    const __half* pB1  = Bg_  + (size_t)(nt * 128 + r1) * K + c1 * 8;

    auto issue = [&](int slot) {
        const uint32_t st = sb + slot * STG_BYTES;
        cp16(st + so0,                 pAh0);
        cp16(st + so1,                 pAh1);
        cp16(st + TEN_BYTES + so0,     pAl0);
        cp16(st + TEN_BYTES + so1,     pAl1);
        cp16(st + 2 * TEN_BYTES + so0, pB0);
        cp16(st + 2 * TEN_BYTES + so1, pB1);
        CP_COMMIT();
        pAh0 += KC; pAh1 += KC; pAl0 += KC; pAl1 += KC;
        pB0  += KC; pB1  += KC;
    };

    // ---- hoisted ldmatrix offsets (ks=0); second k-step = offset ^ 32 ----
    const int lr = lane & 15;
    const int lc = lane >> 4;
    uint32_t aoff[4], boff[2];
    #pragma unroll
    for (int i = 0; i < 4; i++)
        aoff[i] = swz((uint32_t)(warpM * 64 + i * 16 + lr), (uint32_t)lc);
    #pragma unroll
    for (int jj = 0; jj < 2; jj++)
        boff[jj] = swz((uint32_t)(warpN * 32 + jj * 16 + lr), (uint32_t)lc);

    auto compute = [&](int slot) {
        const uint32_t sAh = sb + slot * STG_BYTES;
        const uint32_t sAl = sAh + TEN_BYTES;
        const uint32_t sB  = sAh + 2 * TEN_BYTES;
        #pragma unroll
        for (int ks = 0; ks < 2; ks++) {
            const uint32_t kx = ks ? 32u : 0u;
            uint32_t ah[4][4], al[4][4], bh[2][4];
            #pragma unroll
            for (int jj = 0; jj < 2; jj++)
                ldsm4(bh[jj], sB + (boff[jj] ^ kx));
            #pragma unroll
            for (int i = 0; i < 4; i++) {
                const uint32_t ao = aoff[i] ^ kx;
                ldsm4(ah[i], sAh + ao);
                ldsm4(al[i], sAl + ao);
            }
            #pragma unroll
            for (int i = 0; i < 4; i++) {
                #pragma unroll
                for (int j = 0; j < 4; j++) {
                    const int jj = j >> 1, sel = j & 1;
                    const uint32_t b0 = bh[jj][sel], b1 = bh[jj][sel + 2];
                    mma_f16(acc[i][j], ah[i], b0, b1);     // Ah*B
                    mma_f16(acc[i][j], al[i], b0, b1);     // Al*B
                }
            }
        }
    };

    // ---- 4-stage cp.async pipeline, loads 3 chunks ahead ----
    // Iter kc: wait(group kc done, <=2 outstanding) -> sync -> issue(kc+3)
    //          -> compute(kc).
    // issue(kc+3) writes slot (kc+3)%4 == (kc-1)%4, used by compute(kc-1);
    // this iteration's barrier ordered all warps past compute(kc-1).
    issue(0);
    issue(1);
    issue(2);
    for (int kc = 0; kc < NKC; kc++) {
        cp_wait<2>();
        __syncthreads();
        if (kc + 3 < NKC) issue((kc + 3) & 3);   // overlaps compute(kc)
        compute(kc & 3);
    }

    // ---- epilogue ----
    #pragma unroll
    for (int i = 0; i < 4; i++) {
        const int row0 = mt * 128 + warpM * 64 + i * 16 + (lane >> 2);
        #pragma unroll
        for (int j = 0; j < 4; j++) {
            const int col = nt * 128 + warpN * 32 + j * 8 + (lane & 3) * 2;
            float2 v0, v1;
            v0.x = acc[i][j][0]; v0.y = acc[i][j][1];   // row0
            v1.x = acc[i][j][2]; v1.y = acc[i][j][3];   // row0 + 8
            if (RELU) {
                const float b0 = bias[col], b1 = bias[col + 1];
                v0.x = fmaxf(v0.x + b0, 0.f); v0.y = fmaxf(v0.y + b1, 0.f);
                v1.x = fmaxf(v1.x + b0, 0.f); v1.y = fmaxf(v1.y + b1, 0.f);
            }
            *reinterpret_cast<float2*>(C + (size_t)row0 * N + col)       = v0;
            *reinterpret_cast<float2*>(C + (size_t)(row0 + 8) * N + col) = v1;
        }
    }
}

// ---------------------------------------------------------------------------
// Input pre-split: fp32 -> fp16 hi/lo (vectorized)
// ---------------------------------------------------------------------------
__global__ void split_input(const float* __restrict__ in,
                            __half* __restrict__ h,
                            __half* __restrict__ l)
{
    const size_t i4 = (size_t)blockIdx.x * 256 + threadIdx.x;  // float4 index
    const float4 v = ld4(in + i4 * 4);
    __half hx = __float2half(v.x);
    __half hy = __float2half(v.y);
    __half hz = __float2half(v.z);
    __half hw = __float2half(v.w);
    __half lx = __float2half(v.x - __half2float(hx));
    __half ly = __float2half(v.y - __half2float(hy));
    __half lz = __float2half(v.z - __half2float(hz));
    __half lw = __float2half(v.w - __half2float(hw));
    uint2 hv, lv;
    hv.x = (uint32_t)__half_as_ushort(hx) | ((uint32_t)__half_as_ushort(hy) << 16);
    hv.y = (uint32_t)__half_as_ushort(hz) | ((uint32_t)__half_as_ushort(hw) << 16);
    lv.x = (uint32_t)__half_as_ushort(lx) | ((uint32_t)__half_as_ushort(ly) << 16);
    lv.y = (uint32_t)__half_as_ushort(lz) | ((uint32_t)__half_as_ushort(lw) << 16);
    *reinterpret_cast<uint2*>(h + i4 * 4) = hv;
    *reinterpret_cast<uint2*>(l + i4 * 4) = lv;
}

// ---------------------------------------------------------------------------
// Weight prep: transpose + fp16 convert (single precision term)
// ---------------------------------------------------------------------------
__global__ void prep_w1(const float* __restrict__ W,   // W_lin [1024,512]
                        __half* __restrict__ b)
{
    const int idx = blockIdx.x * 256 + threadIdx.x;
    if (idx >= DPRJ * DIN) return;
    const int n = idx / DIN, k = idx % DIN;
    b[idx] = __float2half(W[(size_t)k * DPRJ + n]);
}

__global__ void prep_w2(const float* __restrict__ W,   // W_aff [512,1024]
                        __half* __restrict__ b)
{
    const int idx = blockIdx.x * 256 + threadIdx.x;
    if (idx >= DOUT * DPRJ) return;
    const int o = idx / DPRJ, p = idx % DPRJ;
    b[idx] = __float2half(W[(size_t)p * DOUT + o]);
}

// ---------------------------------------------------------------------------
// Depthwise causal conv (L=20) + residual; emits m as fp16 hi/lo directly
// ---------------------------------------------------------------------------
#define TCHUNK 128

__global__ __launch_bounds__(256)
void conv_residual_kernel(const float* __restrict__ x,
                          const float* __restrict__ in_cache,
                          const float* __restrict__ conv_w,
                          __half* __restrict__ mh,
                          __half* __restrict__ ml)
{
    const int p  = blockIdx.x * 256 + threadIdx.x;
    const int b  = blockIdx.z;
    const int t0 = blockIdx.y * TCHUNK;

    float w[LORD];
    #pragma unroll
    for (int l = 0; l < LORD; l++) w[l] = conv_w[p * LORD + l];

    float win[LORD - 1];
    #pragma unroll
    for (int i = 0; i < LORD - 1; i++) {
        const int j = t0 - (LORD - 1) + i;
        if (j >= 0)
            win[i] = x[((size_t)b * T_ + j) * DPRJ + p];
        else
            win[i] = in_cache[((size_t)b * DPRJ + p) * (LORD - 1) + (j + LORD - 1)];
    }

    const float* xrow = x  + ((size_t)b * T_ + t0) * DPRJ + p;
    __half* mhrow = mh + ((size_t)b * T_ + t0) * DPRJ + p;
    __half* mlrow = ml + ((size_t)b * T_ + t0) * DPRJ + p;

    for (int t = 0; t < TCHUNK; t++) {
        const float xv = xrow[(size_t)t * DPRJ];
        float acc = fmaf(w[LORD - 1], xv, xv);
        #pragma unroll
        for (int l = 0; l < LORD - 1; l++)
            acc = fmaf(w[l], win[l], acc);
        const __half h = __float2half(acc);
        mhrow[(size_t)t * DPRJ] = h;
        mlrow[(size_t)t * DPRJ] = __float2half(acc - __half2float(h));
        #pragma unroll
        for (int i = 0; i < LORD - 2; i++) win[i] = win[i + 1];
        win[LORD - 2] = xv;
    }
}

__global__ void cache_kernel(const float* __restrict__ x,
                             float* __restrict__ out_cache)
{
    const int idx = blockIdx.x * blockDim.x + threadIdx.x;
    const int total = B_ * DPRJ * (LORD - 1);
    if (idx >= total) return;
    const int i = idx % (LORD - 1);
    const int p = (idx / (LORD - 1)) % DPRJ;
    const int b = idx / ((LORD - 1) * DPRJ);
    out_cache[idx] = x[((size_t)b * T_ + (T_ - (LORD - 1) + i)) * DPRJ + p];
}

// ---------------------------------------------------------------------------
extern "C" void kernel_launch(void* const* d_in, const int* in_sizes, int n_in,
                              void* d_out, int out_size)
{
    const float* input    = (const float*)d_in[0];  // [16, 2048, 1024]
    const float* in_cache = (const float*)d_in[1];  // [16, 512, 19]
    const float* W_lin    = (const float*)d_in[2];  // [1024, 512]
    const float* conv_w   = (const float*)d_in[3];  // [512, 20]
    const float* W_aff    = (const float*)d_in[4];  // [512, 1024]
    const float* b_aff    = (const float*)d_in[5];  // [1024]

    float* out       = (float*)d_out;
    float* out_cache = out + (size_t)B_ * T_ * DOUT;

    float *xbuf;
    __half *a1h, *a1l, *mh, *ml, *b1, *b2;
    cudaGetSymbolAddress((void**)&xbuf, g_x);
    cudaGetSymbolAddress((void**)&a1h, g_a1h);
    cudaGetSymbolAddress((void**)&a1l, g_a1l);
    cudaGetSymbolAddress((void**)&mh,  g_mh);
    cudaGetSymbolAddress((void**)&ml,  g_ml);
    cudaGetSymbolAddress((void**)&b1,  g_b1);
    cudaGetSymbolAddress((void**)&b2,  g_b2);

    const int SMEM_SZ = STAGES * STG_BYTES;   // 98304 B -> 2 CTAs/SM
    cudaFuncSetAttribute(gemm_mma<false>, cudaFuncAttributeMaxDynamicSharedMemorySize, SMEM_SZ);
    cudaFuncSetAttribute(gemm_mma<true>,  cudaFuncAttributeMaxDynamicSharedMemorySize, SMEM_SZ);

    // 0) operand prep: input split + weight transpose/convert
    split_input<<<(MROWS * (size_t)DIN / 4 + 255) / 256, 256>>>(input, a1h, a1l);
    prep_w1<<<(DPRJ * DIN + 255) / 256, 256>>>(W_lin, b1);
    prep_w2<<<(DOUT * DPRJ + 255) / 256, 256>>>(W_aff, b2);

    // 1) x = input @ W_lin      M=32768, N=512, K=1024
    {
        dim3 grid(DPRJ / 128, MROWS / 128);
        gemm_mma<false><<<grid, 256, SMEM_SZ>>>(MROWS, DPRJ, DIN,
                                                a1h, a1l, b1, nullptr, xbuf);
    }

    // 2) m = depthwise_conv(x) + x  (fp16 split out) ; out_cache
    {
        dim3 grid(DPRJ / 256, T_ / TCHUNK, B_);
        conv_residual_kernel<<<grid, 256>>>(xbuf, in_cache, conv_w, mh, ml);
        const int total = B_ * DPRJ * (LORD - 1);
        cache_kernel<<<(total + 255) / 256, 256>>>(xbuf, out_cache);
    }

    // 3) out = relu(m @ W_aff + b_aff)   M=32768, N=1024, K=512
    {
        dim3 grid(DOUT / 128, MROWS / 128);
        gemm_mma<true><<<grid, 256, SMEM_SZ>>>(MROWS, DOUT, DPRJ,
                                               mh, ml, b2, b_aff, out);
    }
}

// round 17
// speedup vs baseline: 1.8271x; 1.0923x over previous
#include <cuda_runtime.h>
#include <cuda_fp16.h>
#include <cstdint>

// Problem constants
#define B_   16
#define T_   2048
#define DIN  1024
#define DPRJ 512
#define DOUT 1024
#define LORD 20
#define MROWS (B_ * T_)          // 32768

// ---------------------------------------------------------------------------
// Device scratch (allocation-free)
// ---------------------------------------------------------------------------
__device__ float g_x[(size_t)MROWS * DPRJ];          // x fp32 (conv in, out_cache)
__device__ __half g_a1[(size_t)MROWS * DIN];         // input fp16 (single)
__device__ __half g_m1[(size_t)MROWS * DPRJ];        // m fp16 (single)
// Transposed weights, fp16 hi/lo split: rows = N dim, K contiguous
__device__ __half g_b1h[(size_t)DPRJ * DIN];         // [512][1024]
__device__ __half g_b1l[(size_t)DPRJ * DIN];
__device__ __half g_b2h[(size_t)DOUT * DPRJ];        // [1024][512]
__device__ __half g_b2l[(size_t)DOUT * DPRJ];

__device__ __forceinline__ float4 ld4(const float* p) {
    return *reinterpret_cast<const float4*>(p);
}

__device__ __forceinline__ uint32_t smem_u32(const void* p) {
    uint32_t a;
    asm("{ .reg .u64 t; cvta.to.shared.u64 t, %1; cvt.u32.u64 %0, t; }"
        : "=r"(a) : "l"(p));
    return a;
}

// cp.async 16B global -> shared
__device__ __forceinline__ void cp16(uint32_t dst, const void* src) {
    asm volatile("cp.async.cg.shared.global [%0], [%1], 16;"
                 :: "r"(dst), "l"(src));
}
#define CP_COMMIT() asm volatile("cp.async.commit_group;" ::: "memory")
template <int N>
__device__ __forceinline__ void cp_wait() {
    asm volatile("cp.async.wait_group %0;" :: "n"(N) : "memory");
}

// ldmatrix x4 (four 8x8 b16 matrices)
__device__ __forceinline__ void ldsm4(uint32_t* r, uint32_t addr) {
    asm volatile("ldmatrix.sync.aligned.m8n8.x4.shared.b16 {%0,%1,%2,%3}, [%4];"
                 : "=r"(r[0]), "=r"(r[1]), "=r"(r[2]), "=r"(r[3])
                 : "r"(addr));
}

// mma.sync m16n8k16 fp16 -> f32
__device__ __forceinline__ void mma_f16(float* c, const uint32_t* a,
                                        uint32_t b0, uint32_t b1) {
    asm volatile(
        "mma.sync.aligned.m16n8k16.row.col.f32.f16.f16.f32 "
        "{%0,%1,%2,%3}, {%4,%5,%6,%7}, {%8,%9}, {%0,%1,%2,%3};"
        : "+f"(c[0]), "+f"(c[1]), "+f"(c[2]), "+f"(c[3])
        : "r"(a[0]), "r"(a[1]), "r"(a[2]), "r"(a[3]), "r"(b0), "r"(b1));
}

// SW128-style swizzle for 128B rows (64 halfs), 16B granules (8 per row):
// granule' = c16 ^ (r & 7).  Conflict-free for ldmatrix 8-row phases and
// cp.async warp stores.  Identity: swz(r, c + 2k) == swz(r, c) ^ (k*32)
// for c in {0,1}, 2k in {0,2,4,6}.
__device__ __forceinline__ uint32_t swz(uint32_t r, uint32_t c16) {
    return r * 128 + (((c16 ^ (r & 7)) & 7) << 4);
}

// ---------------------------------------------------------------------------
// Tensor-core GEMM via mma.sync: C[M,N] = A[M,K] * B^T
// 2-term fp16 split on B: B = Bh + Bl; A single fp16; fp32 accum.
// cp.async double-buffered, KC=64 chunks, 2 CTAs/SM.
// CTA 128x128, 256 threads (8 warps, 2x4), warp tile 64x32.
// SMEM stage: A, Bh, Bl each [128][64] fp16, swizzled 128B rows.
// ---------------------------------------------------------------------------
#define KC        64
#define TEN_BYTES (128 * 64 * 2)          // 16384
#define STG_BYTES (3 * TEN_BYTES)         // 49152
#define STAGES    2                       // 98304 B/CTA -> 2 CTAs/SM

template <bool RELU>
__global__ __launch_bounds__(256, 2)
void gemm_mma(int M, int N, int K,
              const __half* __restrict__ Ag_,
              const __half* __restrict__ Bhg_,
              const __half* __restrict__ Blg_,
              const float* __restrict__ bias,
              float* __restrict__ C)
{
    extern __shared__ char smem_raw[];
    const uint32_t sb = smem_u32(smem_raw);

    const int tid  = threadIdx.x;
    const int lane = tid & 31;
    const int wid  = tid >> 5;
    const int warpM = wid >> 2;           // 0..1
    const int warpN = wid & 3;            // 0..3
    const int nt = blockIdx.x;
    const int mt = blockIdx.y;
    const int NKC = K / KC;

    float acc[4][4][4];
    #pragma unroll
    for (int i = 0; i < 4; i++)
        #pragma unroll
        for (int j = 0; j < 4; j++)
            #pragma unroll
            for (int q = 0; q < 4; q++) acc[i][j][q] = 0.f;

    // ---- cp.async geometry: [128][64] fp16 = 1024 granules of 16B;
    //      4 granules per thread.  Same mapping for all 3 tensors. ----
    uint32_t so[4]; uint32_t off[4];
    #pragma unroll
    for (int it = 0; it < 4; it++) {
        const int i = tid + it * 256;
        const int r = i >> 3, c = i & 7;
        so[it]  = swz((uint32_t)r, (uint32_t)c);
        off[it] = (uint32_t)(r * K + c * 8);
    }
    const __half* pA  = Ag_  + (size_t)mt * 128 * K;
    const __half* pBh = Bhg_ + (size_t)nt * 128 * K;
    const __half* pBl = Blg_ + (size_t)nt * 128 * K;

    auto issue = [&](int slot) {
        const uint32_t st = sb + slot * STG_BYTES;
        #pragma unroll
        for (int it = 0; it < 4; it++) cp16(st + so[it], pA + off[it]);
        #pragma unroll
        for (int it = 0; it < 4; it++) cp16(st + TEN_BYTES + so[it], pBh + off[it]);
        #pragma unroll
        for (int it = 0; it < 4; it++) cp16(st + 2 * TEN_BYTES + so[it], pBl + off[it]);
        CP_COMMIT();
        pA += KC; pBh += KC; pBl += KC;
    };

    // ---- hoisted ldmatrix offsets (ks=0); k-step ks = offset ^ (ks*32) ----
    const int lr = lane & 15;
    const int lc = lane >> 4;
    uint32_t aoff[4], boff[2];
    #pragma unroll
    for (int i = 0; i < 4; i++)
        aoff[i] = swz((uint32_t)(warpM * 64 + i * 16 + lr), (uint32_t)lc);
    #pragma unroll
    for (int jj = 0; jj < 2; jj++)
        boff[jj] = swz((uint32_t)(warpN * 32 + jj * 16 + lr), (uint32_t)lc);

    auto compute = [&](int slot) {
        const uint32_t sA  = sb + slot * STG_BYTES;
        const uint32_t sBh = sA + TEN_BYTES;
        const uint32_t sBl = sA + 2 * TEN_BYTES;
        #pragma unroll
        for (int ks = 0; ks < 4; ks++) {
            const uint32_t kx = (uint32_t)ks * 32u;
            uint32_t a[4][4], bh[2][4], bl[2][4];
            #pragma unroll
            for (int jj = 0; jj < 2; jj++) {
                const uint32_t bo = boff[jj] ^ kx;
                ldsm4(bh[jj], sBh + bo);
                ldsm4(bl[jj], sBl + bo);
            }
            #pragma unroll
            for (int i = 0; i < 4; i++)
                ldsm4(a[i], sA + (aoff[i] ^ kx));
            #pragma unroll
            for (int i = 0; i < 4; i++) {
                #pragma unroll
                for (int j = 0; j < 4; j++) {
                    const int jj = j >> 1, sel = j & 1;
                    mma_f16(acc[i][j], a[i], bh[jj][sel], bh[jj][sel + 2]);  // A*Bh
                    mma_f16(acc[i][j], a[i], bl[jj][sel], bl[jj][sel + 2]);  // A*Bl
                }
            }
        }
    };

    // ---- double-buffered pipeline, KC=64 grain ----
    // Per chunk: wait-all -> sync -> issue(kc+1) -> compute(kc).
    // issue(kc+1) writes the buffer compute(kc-1) used; the barrier at the
    // top of this iteration ordered all warps past compute(kc-1).
    issue(0);
    for (int kc = 0; kc < NKC; kc++) {
        cp_wait<0>();
        __syncthreads();
        if (kc + 1 < NKC) issue((kc + 1) & 1);   // overlaps compute(kc)
        compute(kc & 1);
    }

    // ---- epilogue ----
    #pragma unroll
    for (int i = 0; i < 4; i++) {
        const int row0 = mt * 128 + warpM * 64 + i * 16 + (lane >> 2);
        #pragma unroll
        for (int j = 0; j < 4; j++) {
            const int col = nt * 128 + warpN * 32 + j * 8 + (lane & 3) * 2;
            float2 v0, v1;
            v0.x = acc[i][j][0]; v0.y = acc[i][j][1];   // row0
            v1.x = acc[i][j][2]; v1.y = acc[i][j][3];   // row0 + 8
            if (RELU) {
                const float b0 = bias[col], b1 = bias[col + 1];
                v0.x = fmaxf(v0.x + b0, 0.f); v0.y = fmaxf(v0.y + b1, 0.f);
                v1.x = fmaxf(v1.x + b0, 0.f); v1.y = fmaxf(v1.y + b1, 0.f);
            }
            *reinterpret_cast<float2*>(C + (size_t)row0 * N + col)       = v0;
            *reinterpret_cast<float2*>(C + (size_t)(row0 + 8) * N + col) = v1;
        }
    }
}

// ---------------------------------------------------------------------------
// Input convert: fp32 -> fp16 (single, vectorized)
// ---------------------------------------------------------------------------
__global__ void convert_input(const float* __restrict__ in,
                              __half* __restrict__ h)
{
    const size_t i4 = (size_t)blockIdx.x * 256 + threadIdx.x;  // float4 index
    const float4 v = ld4(in + i4 * 4);
    uint2 hv;
    hv.x = (uint32_t)__half_as_ushort(__float2half(v.x)) |
           ((uint32_t)__half_as_ushort(__float2half(v.y)) << 16);
    hv.y = (uint32_t)__half_as_ushort(__float2half(v.z)) |
           ((uint32_t)__half_as_ushort(__float2half(v.w)) << 16);
    *reinterpret_cast<uint2*>(h + i4 * 4) = hv;
}

// ---------------------------------------------------------------------------
// Weight prep: transpose + fp16 hi/lo split
// ---------------------------------------------------------------------------
__global__ void prep_w1(const float* __restrict__ W,   // W_lin [1024,512]
                        __half* __restrict__ bh,
                        __half* __restrict__ bl)
{
    const int idx = blockIdx.x * 256 + threadIdx.x;
    if (idx >= DPRJ * DIN) return;
    const int n = idx / DIN, k = idx % DIN;
    const float v = W[(size_t)k * DPRJ + n];
    const __half h = __float2half(v);
    bh[idx] = h;
    bl[idx] = __float2half(v - __half2float(h));
}

__global__ void prep_w2(const float* __restrict__ W,   // W_aff [512,1024]
                        __half* __restrict__ bh,
                        __half* __restrict__ bl)
{
    const int idx = blockIdx.x * 256 + threadIdx.x;
    if (idx >= DOUT * DPRJ) return;
    const int o = idx / DPRJ, p = idx % DPRJ;
    const float v = W[(size_t)p * DOUT + o];
    const __half h = __float2half(v);
    bh[idx] = h;
    bl[idx] = __float2half(v - __half2float(h));
}

// ---------------------------------------------------------------------------
// Depthwise causal conv (L=20) + residual; emits m as single fp16
// ---------------------------------------------------------------------------
#define TCHUNK 128

__global__ __launch_bounds__(256)
void conv_residual_kernel(const float* __restrict__ x,
                          const float* __restrict__ in_cache,
                          const float* __restrict__ conv_w,
                          __half* __restrict__ m1)
{
    const int p  = blockIdx.x * 256 + threadIdx.x;
    const int b  = blockIdx.z;
    const int t0 = blockIdx.y * TCHUNK;

    float w[LORD];
    #pragma unroll
    for (int l = 0; l < LORD; l++) w[l] = conv_w[p * LORD + l];

    float win[LORD - 1];
    #pragma unroll
    for (int i = 0; i < LORD - 1; i++) {
        const int j = t0 - (LORD - 1) + i;
        if (j >= 0)
            win[i] = x[((size_t)b * T_ + j) * DPRJ + p];
        else
            win[i] = in_cache[((size_t)b * DPRJ + p) * (LORD - 1) + (j + LORD - 1)];
    }

    const float* xrow = x  + ((size_t)b * T_ + t0) * DPRJ + p;
    __half* mrow = m1 + ((size_t)b * T_ + t0) * DPRJ + p;

    for (int t = 0; t < TCHUNK; t++) {
        const float xv = xrow[(size_t)t * DPRJ];
        float acc = fmaf(w[LORD - 1], xv, xv);
        #pragma unroll
        for (int l = 0; l < LORD - 1; l++)
            acc = fmaf(w[l], win[l], acc);
        mrow[(size_t)t * DPRJ] = __float2half(acc);
        #pragma unroll
        for (int i = 0; i < LORD - 2; i++) win[i] = win[i + 1];
        win[LORD - 2] = xv;
    }
}

__global__ void cache_kernel(const float* __restrict__ x,
                             float* __restrict__ out_cache)
{
    const int idx = blockIdx.x * blockDim.x + threadIdx.x;
    const int total = B_ * DPRJ * (LORD - 1);
    if (idx >= total) return;
    const int i = idx % (LORD - 1);
    const int p = (idx / (LORD - 1)) % DPRJ;
    const int b = idx / ((LORD - 1) * DPRJ);
    out_cache[idx] = x[((size_t)b * T_ + (T_ - (LORD - 1) + i)) * DPRJ + p];
}

// ---------------------------------------------------------------------------
extern "C" void kernel_launch(void* const* d_in, const int* in_sizes, int n_in,
                              void* d_out, int out_size)
{
    const float* input    = (const float*)d_in[0];  // [16, 2048, 1024]
    const float* in_cache = (const float*)d_in[1];  // [16, 512, 19]
    const float* W_lin    = (const float*)d_in[2];  // [1024, 512]
    const float* conv_w   = (const float*)d_in[3];  // [512, 20]
    const float* W_aff    = (const float*)d_in[4];  // [512, 1024]
    const float* b_aff    = (const float*)d_in[5];  // [1024]

    float* out       = (float*)d_out;
    float* out_cache = out + (size_t)B_ * T_ * DOUT;

    float *xbuf;
    __half *a1, *m1, *b1h, *b1l, *b2h, *b2l;
    cudaGetSymbolAddress((void**)&xbuf, g_x);
    cudaGetSymbolAddress((void**)&a1,  g_a1);
    cudaGetSymbolAddress((void**)&m1,  g_m1);
    cudaGetSymbolAddress((void**)&b1h, g_b1h);
    cudaGetSymbolAddress((void**)&b1l, g_b1l);
    cudaGetSymbolAddress((void**)&b2h, g_b2h);
    cudaGetSymbolAddress((void**)&b2l, g_b2l);

    const int SMEM_SZ = STAGES * STG_BYTES;   // 98304 B -> 2 CTAs/SM
    cudaFuncSetAttribute(gemm_mma<false>, cudaFuncAttributeMaxDynamicSharedMemorySize, SMEM_SZ);
    cudaFuncSetAttribute(gemm_mma<true>,  cudaFuncAttributeMaxDynamicSharedMemorySize, SMEM_SZ);

    // 0) operand prep: input convert + weight transpose/split
    convert_input<<<(MROWS * (size_t)DIN / 4 + 255) / 256, 256>>>(input, a1);
    prep_w1<<<(DPRJ * DIN + 255) / 256, 256>>>(W_lin, b1h, b1l);
    prep_w2<<<(DOUT * DPRJ + 255) / 256, 256>>>(W_aff, b2h, b2l);

    // 1) x = input @ W_lin      M=32768, N=512, K=1024
    {
        dim3 grid(DPRJ / 128, MROWS / 128);
        gemm_mma<false><<<grid, 256, SMEM_SZ>>>(MROWS, DPRJ, DIN,
                                                a1, b1h, b1l, nullptr, xbuf);
    }

    // 2) m = depthwise_conv(x) + x  (fp16 out) ; out_cache
    {
        dim3 grid(DPRJ / 256, T_ / TCHUNK, B_);
        conv_residual_kernel<<<grid, 256>>>(xbuf, in_cache, conv_w, m1);
        const int total = B_ * DPRJ * (LORD - 1);
        cache_kernel<<<(total + 255) / 256, 256>>>(xbuf, out_cache);
    }

    // 3) out = relu(m @ W_aff + b_aff)   M=32768, N=1024, K=512
    {
        dim3 grid(DOUT / 128, MROWS / 128);
        gemm_mma<true><<<grid, 256, SMEM_SZ>>>(MROWS, DOUT, DPRJ,
                                               m1, b2h, b2l, b_aff, out);
    }
}